// round 7
// baseline (speedup 1.0000x reference)
#include <cuda_runtime.h>
#include <math.h>

// Problem constants
constexpr int B_  = 2;
constexpr int T_  = 2048;
constexpr int C_  = 768;
constexpr int NH_ = 12;
constexpr int HS_ = 64;
constexpr int M_  = B_ * T_;      // 4096
constexpr int N3_ = 3 * C_;       // 2304
constexpr int K_  = C_;           // 768

typedef unsigned long long ull;

// Packed fp32x2 helpers (sm_103a FFMA2 — only reachable via PTX)
__device__ __forceinline__ ull dup2(float x) {
    ull r; asm("mov.b64 %0, {%1, %1};" : "=l"(r) : "f"(x)); return r;
}
__device__ __forceinline__ void fma2(ull& d, ull a, ull b) {
    asm("fma.rn.f32x2 %0, %1, %2, %0;" : "+l"(d) : "l"(a), "l"(b));
}
__device__ __forceinline__ void mul2(ull& d, ull a, ull b) {
    asm("mul.rn.f32x2 %0, %1, %2;" : "=l"(d) : "l"(a), "l"(b));
}
__device__ __forceinline__ float2 unpk(ull v) {
    float2 f; asm("mov.b64 {%0, %1}, %2;" : "=f"(f.x), "=f"(f.y) : "l"(v));
    return f;
}

// Scratch Q/K/V in [B, NH, T, HS] layout
__device__ float g_q[(size_t)B_ * NH_ * T_ * HS_];
__device__ float g_k[(size_t)B_ * NH_ * T_ * HS_];
__device__ float g_v[(size_t)B_ * NH_ * T_ * HS_];

// ---------------------------------------------------------------------------
// Kernel 1: qkv = x @ w + b, f32x2 inner loop, double-buffered smem.
// 128x128 tile, BK=8, 256 threads, 8x8 register blocking.
// ---------------------------------------------------------------------------
__global__ __launch_bounds__(256) void qkv_gemm_kernel(
    const float* __restrict__ x,      // [M_, K_]
    const float* __restrict__ w,      // [K_, N3_]
    const float* __restrict__ bias)   // [N3_]
{
    __shared__ float As[2][8][128];   // As[buf][k][m]
    __shared__ float Bs[2][8][128];   // Bs[buf][k][n]

    const int tid = threadIdx.x;
    const int m0 = blockIdx.y * 128;
    const int n0 = blockIdx.x * 128;
    const int ty = tid / 16;
    const int tx = tid % 16;

    const int arow = tid >> 1;
    const int acol = (tid & 1) * 4;
    const int brow = tid >> 5;
    const int bcol = (tid & 31) * 4;

    ull acc[8][4];
#pragma unroll
    for (int i = 0; i < 8; i++)
#pragma unroll
        for (int p = 0; p < 4; p++) acc[i][p] = 0ULL;

    // prologue: tile 0 -> buf 0
    {
        float4 av = *reinterpret_cast<const float4*>(
            &x[(size_t)(m0 + arow) * K_ + acol]);
        As[0][acol + 0][arow] = av.x;
        As[0][acol + 1][arow] = av.y;
        As[0][acol + 2][arow] = av.z;
        As[0][acol + 3][arow] = av.w;
        *reinterpret_cast<float4*>(&Bs[0][brow][bcol]) =
            *reinterpret_cast<const float4*>(&w[(size_t)brow * N3_ + n0 + bcol]);
    }
    __syncthreads();

    int buf = 0;
    for (int k0 = 0; k0 < K_; k0 += 8) {
        const bool has_next = (k0 + 8 < K_);
        float4 av2, bv2;
        if (has_next) {
            av2 = *reinterpret_cast<const float4*>(
                &x[(size_t)(m0 + arow) * K_ + k0 + 8 + acol]);
            bv2 = *reinterpret_cast<const float4*>(
                &w[(size_t)(k0 + 8 + brow) * N3_ + n0 + bcol]);
        }

#pragma unroll
        for (int k = 0; k < 8; k++) {
            float af[8];
            *reinterpret_cast<float4*>(&af[0]) =
                *reinterpret_cast<const float4*>(&As[buf][k][ty * 8]);
            *reinterpret_cast<float4*>(&af[4]) =
                *reinterpret_cast<const float4*>(&As[buf][k][ty * 8 + 4]);
            ulonglong2 bA = *reinterpret_cast<const ulonglong2*>(&Bs[buf][k][4 * tx]);
            ulonglong2 bB = *reinterpret_cast<const ulonglong2*>(&Bs[buf][k][64 + 4 * tx]);
#pragma unroll
            for (int i = 0; i < 8; i++) {
                ull aa = dup2(af[i]);
                fma2(acc[i][0], aa, bA.x);
                fma2(acc[i][1], aa, bA.y);
                fma2(acc[i][2], aa, bB.x);
                fma2(acc[i][3], aa, bB.y);
            }
        }

        if (has_next) {
            const int nb = buf ^ 1;
            As[nb][acol + 0][arow] = av2.x;
            As[nb][acol + 1][arow] = av2.y;
            As[nb][acol + 2][arow] = av2.z;
            As[nb][acol + 3][arow] = av2.w;
            *reinterpret_cast<float4*>(&Bs[nb][brow][bcol]) = bv2;
            __syncthreads();
        }
        buf ^= 1;
    }

    // Epilogue: bias + scatter to [B, NH, T, HS]
#pragma unroll
    for (int i = 0; i < 8; i++) {
        const int m = m0 + ty * 8 + i;
        const int bb = m / T_;
        const int t  = m % T_;
#pragma unroll
        for (int p = 0; p < 4; p++) {
            const int c0 = (p < 2) ? (4 * tx + 2 * p) : (64 + 4 * tx + 2 * (p - 2));
            float2 f = unpk(acc[i][p]);
            float vv[2] = {f.x, f.y};
#pragma unroll
            for (int half = 0; half < 2; half++) {
                const int n = n0 + c0 + half;
                const float val = vv[half] + bias[n];
                const int which = n / C_;
                const int wn    = n - which * C_;
                const int head  = wn / HS_;
                const int d     = wn % HS_;
                float* dst = (which == 0) ? g_q : (which == 1) ? g_k : g_v;
                dst[(((size_t)bb * NH_ + head) * T_ + t) * HS_ + d] = val;
            }
        }
    }
}

// ---------------------------------------------------------------------------
// Kernel 2: flash-style causal attention.
// BR=64 q-rows, BC=64 keys, 128 threads/CTA, 8x4 register tile + f32x2.
// ty=tid/16 (rows 8ty..+7), tx=tid%16 (cols 4tx..+3).
// launch_bounds(128,3): 3 CTAs/SM (12 warps) -> barrier/LDG stalls overlap.
// ---------------------------------------------------------------------------
constexpr int BR  = 64;
constexpr int BC  = 64;
constexpr int LDA = 68;                                        // padded stride
constexpr int ATTN_SMEM = (BR + BC + BC + BR) * LDA * (int)sizeof(float); // 69632

__global__ __launch_bounds__(128, 3) void attn_kernel(float* __restrict__ out)
{
    extern __shared__ float sm[];
    float* Qs = sm;                   // [row][d]   row-major
    float* Kt = Qs + BR * LDA;        // [d][key]   transposed
    float* Vs = Kt + BC * LDA;        // [key][d]   row-major
    float* Ps = Vs + BC * LDA;        // [row][key] row-major

    const int tid = threadIdx.x;
    const int qt  = (T_ / BR) - 1 - blockIdx.x;   // heavy tiles first
    const int h   = blockIdx.y;
    const int b   = blockIdx.z;
    const size_t base = ((size_t)b * NH_ + h) * T_ * HS_;

    const int ty = tid >> 4, tx = tid & 15;
    const int row8 = ty * 8, col4 = tx * 4;

    // cooperative Q tile load: 64 rows x 64, 32 floats per thread
    {
        const int r  = tid >> 1;
        const int cp = (tid & 1) * 32;
        const float* src = g_q + base + (size_t)(qt * BR + r) * HS_ + cp;
        float* dst = Qs + r * LDA + cp;
#pragma unroll
        for (int i = 0; i < 8; i++)
            reinterpret_cast<float4*>(dst)[i] =
                reinterpret_cast<const float4*>(src)[i];
    }

    float m_i[8], l_i[8];
    ull acc[8][2];
#pragma unroll
    for (int i = 0; i < 8; i++) {
        m_i[i] = -INFINITY; l_i[i] = 0.0f;
        acc[i][0] = 0ULL; acc[i][1] = 0ULL;
    }
    const float scale = 0.125f;

    for (int j = 0; j <= qt; j++) {
        __syncthreads();   // everyone done reading previous K/V
        // load K (transposed, permuted store) and V; 2 rows per thread
        {
            const int r0 = tid >> 2;           // 0..31
            const int cp = (tid & 3) * 16;
            const int ph = tid & 3;
#pragma unroll
            for (int rr = 0; rr < 2; rr++) {
                const int r = r0 + rr * 32;
                const float* ksrc = g_k + base + (size_t)(j * BC + r) * HS_ + cp;
                const float* vsrc = g_v + base + (size_t)(j * BC + r) * HS_ + cp;
                float ka[16];
#pragma unroll
                for (int i = 0; i < 4; i++) {
                    *reinterpret_cast<float4*>(&ka[4 * i]) =
                        reinterpret_cast<const float4*>(ksrc)[i];
                    reinterpret_cast<float4*>(Vs + r * LDA + cp)[i] =
                        reinterpret_cast<const float4*>(vsrc)[i];
                }
#pragma unroll
                for (int c = 0; c < 16; c++) {
                    const int c2 = (c + ph) & 15;   // break 4-way bank conflict
                    Kt[(cp + c2) * LDA + r] = ka[c2];
                }
            }
        }
        __syncthreads();

        // ---- S = Q K^T : 8x4 register tile ----
        ull sp[8][2];
#pragma unroll
        for (int i = 0; i < 8; i++) { sp[i][0] = 0ULL; sp[i][1] = 0ULL; }

#pragma unroll 2
        for (int d0 = 0; d0 < HS_; d0 += 4) {
            ulonglong2 kb[4];
#pragma unroll
            for (int u = 0; u < 4; u++)
                kb[u] = *reinterpret_cast<const ulonglong2*>(
                    Kt + (d0 + u) * LDA + col4);
#pragma unroll
            for (int hlf = 0; hlf < 2; hlf++) {
                float aq[4][4];
#pragma unroll
                for (int i = 0; i < 4; i++)
                    *reinterpret_cast<float4*>(aq[i]) =
                        *reinterpret_cast<const float4*>(
                            Qs + (row8 + hlf * 4 + i) * LDA + d0);
#pragma unroll
                for (int u = 0; u < 4; u++)
#pragma unroll
                    for (int i = 0; i < 4; i++) {
                        ull aa = dup2(aq[i][u]);
                        fma2(sp[hlf * 4 + i][0], aa, kb[u].x);
                        fma2(sp[hlf * 4 + i][1], aa, kb[u].y);
                    }
            }
        }

        float s[8][4];
#pragma unroll
        for (int i = 0; i < 8; i++) {
            float2 f0 = unpk(sp[i][0]), f1 = unpk(sp[i][1]);
            s[i][0] = f0.x * scale; s[i][1] = f0.y * scale;
            s[i][2] = f1.x * scale; s[i][3] = f1.y * scale;
        }

        if (j == qt) {                 // diagonal block: causal mask
#pragma unroll
            for (int i = 0; i < 8; i++)
#pragma unroll
                for (int c = 0; c < 4; c++)
                    if (col4 + c > row8 + i) s[i][c] = -INFINITY;
        }

        // ---- online softmax (row stats across the 16 tx lanes) ----
#pragma unroll
        for (int i = 0; i < 8; i++) {
            float mx = fmaxf(fmaxf(s[i][0], s[i][1]), fmaxf(s[i][2], s[i][3]));
            mx = fmaxf(mx, __shfl_xor_sync(0xffffffffu, mx, 1));
            mx = fmaxf(mx, __shfl_xor_sync(0xffffffffu, mx, 2));
            mx = fmaxf(mx, __shfl_xor_sync(0xffffffffu, mx, 4));
            mx = fmaxf(mx, __shfl_xor_sync(0xffffffffu, mx, 8));
            const float mn   = fmaxf(m_i[i], mx);
            const float corr = __expf(m_i[i] - mn);
            m_i[i] = mn;
            float sum = 0.0f;
#pragma unroll
            for (int c = 0; c < 4; c++) {
                const float p = __expf(s[i][c] - mn);
                s[i][c] = p;
                sum += p;
            }
            sum += __shfl_xor_sync(0xffffffffu, sum, 1);
            sum += __shfl_xor_sync(0xffffffffu, sum, 2);
            sum += __shfl_xor_sync(0xffffffffu, sum, 4);
            sum += __shfl_xor_sync(0xffffffffu, sum, 8);
            l_i[i] = l_i[i] * corr + sum;
            ull cc = dup2(corr);
            mul2(acc[i][0], acc[i][0], cc);
            mul2(acc[i][1], acc[i][1], cc);
            *reinterpret_cast<float4*>(Ps + (row8 + i) * LDA + col4) =
                make_float4(s[i][0], s[i][1], s[i][2], s[i][3]);
        }
        __syncwarp();   // all producers of each P row are in this warp

        // ---- O += P V : 8x4 register tile ----
#pragma unroll 2
        for (int kl0 = 0; kl0 < BC; kl0 += 4) {
            ulonglong2 vb[4];
#pragma unroll
            for (int u = 0; u < 4; u++)
                vb[u] = *reinterpret_cast<const ulonglong2*>(
                    Vs + (kl0 + u) * LDA + col4);
#pragma unroll
            for (int hlf = 0; hlf < 2; hlf++) {
                float pa[4][4];
#pragma unroll
                for (int i = 0; i < 4; i++)
                    *reinterpret_cast<float4*>(pa[i]) =
                        *reinterpret_cast<const float4*>(
                            Ps + (row8 + hlf * 4 + i) * LDA + kl0);
#pragma unroll
                for (int u = 0; u < 4; u++)
#pragma unroll
                    for (int i = 0; i < 4; i++) {
                        ull aa = dup2(pa[i][u]);
                        fma2(acc[hlf * 4 + i][0], aa, vb[u].x);
                        fma2(acc[hlf * 4 + i][1], aa, vb[u].y);
                    }
            }
        }
    }

    // ---- normalize + write [B, NH, T, HS] ----
#pragma unroll
    for (int i = 0; i < 8; i++) {
        const float inv = 1.0f / l_i[i];
        float2 f0 = unpk(acc[i][0]), f1 = unpk(acc[i][1]);
        float4 o = make_float4(f0.x * inv, f0.y * inv, f1.x * inv, f1.y * inv);
        *reinterpret_cast<float4*>(
            out + base + (size_t)(qt * BR + row8 + i) * HS_ + col4) = o;
    }
}

// ---------------------------------------------------------------------------
extern "C" void kernel_launch(void* const* d_in, const int* in_sizes, int n_in,
                              void* d_out, int out_size)
{
    (void)in_sizes; (void)n_in; (void)out_size;
    const float* x    = (const float*)d_in[0];
    const float* w    = (const float*)d_in[1];
    const float* bias = (const float*)d_in[2];
    float* out = (float*)d_out;

    dim3 g1(N3_ / 128, M_ / 128);   // (18, 32)
    qkv_gemm_kernel<<<g1, 256>>>(x, w, bias);

    cudaFuncSetAttribute(attn_kernel,
                         cudaFuncAttributeMaxDynamicSharedMemorySize,
                         ATTN_SMEM);
    dim3 g2(T_ / BR, NH_, B_);      // (32, 12, 2)
    attn_kernel<<<g2, 128, ATTN_SMEM>>>(out);
}

// round 9
// speedup vs baseline: 1.2628x; 1.2628x over previous
#include <cuda_runtime.h>
#include <cuda_bf16.h>
#include <math.h>
#include <stdint.h>

// Problem constants
constexpr int B_  = 2;
constexpr int T_  = 2048;
constexpr int C_  = 768;
constexpr int NH_ = 12;
constexpr int HS_ = 64;
constexpr int M_  = B_ * T_;      // 4096
constexpr int N3_ = 3 * C_;       // 2304
constexpr int K_  = C_;           // 768

typedef unsigned long long ull;

// ---------------------------------------------------------------------------
// PTX helpers (base-PTX only: legal at compute_103)
// ---------------------------------------------------------------------------
__device__ __forceinline__ uint32_t smem_u32(const void* p) {
    uint32_t a;
    asm("{ .reg .u64 t; cvta.to.shared.u64 t, %1; cvt.u32.u64 %0, t; }"
        : "=r"(a) : "l"(p));
    return a;
}

#define LDSM4(r0, r1, r2, r3, addr)                                          \
    asm volatile("ldmatrix.sync.aligned.m8n8.x4.shared.b16 {%0,%1,%2,%3}, [%4];" \
                 : "=r"(r0), "=r"(r1), "=r"(r2), "=r"(r3) : "r"(addr))

#define MMA16816(d, a, b0v, b1v)                                             \
    asm volatile("mma.sync.aligned.m16n8k16.row.col.f32.bf16.bf16.f32 "      \
                 "{%0,%1,%2,%3}, {%4,%5,%6,%7}, {%8,%9}, {%0,%1,%2,%3};"     \
                 : "+f"((d)[0]), "+f"((d)[1]), "+f"((d)[2]), "+f"((d)[3])    \
                 : "r"((a)[0]), "r"((a)[1]), "r"((a)[2]), "r"((a)[3]),       \
                   "r"(b0v), "r"(b1v))

#define CP_ASYNC16(dst, src)                                                 \
    asm volatile("cp.async.cg.shared.global [%0], [%1], 16;"                 \
                 :: "r"(dst), "l"(src) : "memory")
#define CP_COMMIT() asm volatile("cp.async.commit_group;" ::: "memory")
#define CP_WAIT0()  asm volatile("cp.async.wait_group 0;" ::: "memory")

// Packed fp32x2 helpers (attention kernel)
__device__ __forceinline__ ull dup2(float x) {
    ull r; asm("mov.b64 %0, {%1, %1};" : "=l"(r) : "f"(x)); return r;
}
__device__ __forceinline__ void fma2(ull& d, ull a, ull b) {
    asm("fma.rn.f32x2 %0, %1, %2, %0;" : "+l"(d) : "l"(a), "l"(b));
}
__device__ __forceinline__ void mul2(ull& d, ull a, ull b) {
    asm("mul.rn.f32x2 %0, %1, %2;" : "=l"(d) : "l"(a), "l"(b));
}
__device__ __forceinline__ float2 unpk(ull v) {
    float2 f; asm("mov.b64 {%0, %1}, %2;" : "=f"(f.x), "=f"(f.y) : "l"(v));
    return f;
}

// ---------------------------------------------------------------------------
// Device scratch
// ---------------------------------------------------------------------------
__device__ float g_q[(size_t)B_ * NH_ * T_ * HS_];
__device__ float g_k[(size_t)B_ * NH_ * T_ * HS_];
__device__ float g_v[(size_t)B_ * NH_ * T_ * HS_];
__device__ __nv_bfloat16 g_xh[(size_t)M_ * K_];
__device__ __nv_bfloat16 g_xl[(size_t)M_ * K_];
__device__ __nv_bfloat16 g_wth[(size_t)N3_ * K_];   // w transposed [N][K]
__device__ __nv_bfloat16 g_wtl[(size_t)N3_ * K_];

// ---------------------------------------------------------------------------
// Convert kernels: fp32 -> bf16 hi/lo split (+ transpose for w)
// ---------------------------------------------------------------------------
__global__ __launch_bounds__(256) void conv_x_kernel(const float* __restrict__ x)
{
    const int idx = blockIdx.x * 256 + threadIdx.x;     // one float4 each
    if (idx >= M_ * K_ / 4) return;
    float4 v = reinterpret_cast<const float4*>(x)[idx];
    float vv[4] = {v.x, v.y, v.z, v.w};
    ushort hs[4], ls[4];
#pragma unroll
    for (int e = 0; e < 4; e++) {
        __nv_bfloat16 h = __float2bfloat16(vv[e]);
        __nv_bfloat16 l = __float2bfloat16(vv[e] - __bfloat162float(h));
        hs[e] = __bfloat16_as_ushort(h);
        ls[e] = __bfloat16_as_ushort(l);
    }
    *reinterpret_cast<ushort4*>(&g_xh[(size_t)idx * 4]) =
        make_ushort4(hs[0], hs[1], hs[2], hs[3]);
    *reinterpret_cast<ushort4*>(&g_xl[(size_t)idx * 4]) =
        make_ushort4(ls[0], ls[1], ls[2], ls[3]);
}

__global__ __launch_bounds__(256) void conv_w_kernel(const float* __restrict__ w)
{
    const int idx = blockIdx.x * 256 + threadIdx.x;     // (k4, n)
    if (idx >= (K_ / 4) * N3_) return;
    const int n  = idx % N3_;
    const int k4 = idx / N3_;
    ushort hs[4], ls[4];
#pragma unroll
    for (int e = 0; e < 4; e++) {
        float v = w[(size_t)(4 * k4 + e) * N3_ + n];
        __nv_bfloat16 h = __float2bfloat16(v);
        __nv_bfloat16 l = __float2bfloat16(v - __bfloat162float(h));
        hs[e] = __bfloat16_as_ushort(h);
        ls[e] = __bfloat16_as_ushort(l);
    }
    *reinterpret_cast<ushort4*>(&g_wth[(size_t)n * K_ + 4 * k4]) =
        make_ushort4(hs[0], hs[1], hs[2], hs[3]);
    *reinterpret_cast<ushort4*>(&g_wtl[(size_t)n * K_ + 4 * k4]) =
        make_ushort4(ls[0], ls[1], ls[2], ls[3]);
}

// ---------------------------------------------------------------------------
// Kernel: HMMA (mma.sync m16n8k16 bf16) 3-term split GEMM.
// CTA tile M=128 x N=128, 256 threads (8 warps, warp tile 32x64).
// K chunks of 32, cp.async double-buffered, padded smem LDK=40 halves.
// ---------------------------------------------------------------------------
constexpr int CH  = 32;               // k per chunk
constexpr int LDK = 40;               // halves per smem row (80B, conflict-free)
constexpr int NCH = K_ / CH;          // 24
constexpr int ARR_BYTES = 128 * LDK * 2;          // 10240
constexpr int BUF_BYTES = 4 * ARR_BYTES;          // 40960
constexpr int OFF_AH = 0;
constexpr int OFF_AL = ARR_BYTES;
constexpr int OFF_BH = 2 * ARR_BYTES;
constexpr int OFF_BL = 3 * ARR_BYTES;
constexpr int GEMM_SMEM = 2 * BUF_BYTES;          // 81920

__global__ __launch_bounds__(256, 1) void qkv_gemm_tc(const float* __restrict__ bias)
{
    extern __shared__ char smem[];
    const uint32_t sb = smem_u32(smem);
    const int tid  = threadIdx.x;
    const int wid  = tid >> 5, lane = tid & 31;
    const int wm   = wid & 3;          // warp rows: wm*32
    const int wn   = wid >> 2;         // warp cols: wn*64
    const int m0   = blockIdx.y * 128;
    const int n0   = blockIdx.x * 128;

    // global-load role: row = tid/2 (0..127), part = tid&1 (16 halves each)
    const int grow = tid >> 1;
    const int gpart = tid & 1;
    const __nv_bfloat16* xh = g_xh + (size_t)(m0 + grow) * K_ + gpart * 16;
    const __nv_bfloat16* xl = g_xl + (size_t)(m0 + grow) * K_ + gpart * 16;
    const __nv_bfloat16* bh = g_wth + (size_t)(n0 + grow) * K_ + gpart * 16;
    const __nv_bfloat16* bl = g_wtl + (size_t)(n0 + grow) * K_ + gpart * 16;
    const uint32_t sdst = sb + (uint32_t)((grow * LDK + gpart * 16) * 2);

    auto issue_loads = [&](int c, int buf) {
        const uint32_t d0 = sdst + buf * BUF_BYTES;
        const int ko = c * CH;
#pragma unroll
        for (int i = 0; i < 2; i++) {
            CP_ASYNC16(d0 + OFF_AH + i * 16, xh + ko + i * 8);
            CP_ASYNC16(d0 + OFF_AL + i * 16, xl + ko + i * 8);
            CP_ASYNC16(d0 + OFF_BH + i * 16, bh + ko + i * 8);
            CP_ASYNC16(d0 + OFF_BL + i * 16, bl + ko + i * 8);
        }
    };

    // ldmatrix lane geometry
    const int t4 = lane >> 3, r8 = lane & 7;
    const int a_moff = (t4 & 1) * 8, a_koff = (t4 >> 1) * 8;
    const int b_noff = (t4 >> 1) * 8, b_koff = (t4 & 1) * 8;

    float d[2][8][4];
#pragma unroll
    for (int mt = 0; mt < 2; mt++)
#pragma unroll
        for (int nt = 0; nt < 8; nt++)
#pragma unroll
            for (int e = 0; e < 4; e++) d[mt][nt][e] = 0.0f;

    issue_loads(0, 0);
    CP_COMMIT();

    for (int c = 0; c < NCH; c++) {
        CP_WAIT0();
        __syncthreads();
        if (c + 1 < NCH) { issue_loads(c + 1, (c + 1) & 1); }
        CP_COMMIT();

        const uint32_t bufb = sb + (uint32_t)((c & 1) * BUF_BYTES);
#pragma unroll
        for (int ks = 0; ks < 2; ks++) {
            uint32_t ah[2][4], al[2][4];
#pragma unroll
            for (int mt = 0; mt < 2; mt++) {
                const uint32_t ad = bufb + OFF_AH +
                    (uint32_t)(((wm * 32 + mt * 16 + a_moff + r8) * LDK +
                                ks * 16 + a_koff) * 2);
                LDSM4(ah[mt][0], ah[mt][1], ah[mt][2], ah[mt][3], ad);
                LDSM4(al[mt][0], al[mt][1], al[mt][2], al[mt][3],
                      ad + (OFF_AL - OFF_AH));
            }
            uint32_t bhf[4][4], blf[4][4];
#pragma unroll
            for (int np = 0; np < 4; np++) {
                const uint32_t bd = bufb + OFF_BH +
                    (uint32_t)(((wn * 64 + np * 16 + b_noff + r8) * LDK +
                                ks * 16 + b_koff) * 2);
                LDSM4(bhf[np][0], bhf[np][1], bhf[np][2], bhf[np][3], bd);
                LDSM4(blf[np][0], blf[np][1], blf[np][2], blf[np][3],
                      bd + (OFF_BL - OFF_BH));
            }
#pragma unroll
            for (int mt = 0; mt < 2; mt++)
#pragma unroll
                for (int nt = 0; nt < 8; nt++) {
                    const int np = nt >> 1, hf = (nt & 1) * 2;
                    MMA16816(d[mt][nt], ah[mt], bhf[np][hf], bhf[np][hf + 1]);
                    MMA16816(d[mt][nt], ah[mt], blf[np][hf], blf[np][hf + 1]);
                    MMA16816(d[mt][nt], al[mt], bhf[np][hf], bhf[np][hf + 1]);
                }
        }
    }

    // Epilogue: bias + scatter to g_q/g_k/g_v [B, NH, T, HS]
    const int g   = lane >> 2, tig = lane & 3;
    const int which = n0 / C_;                      // constant per CTA
    const int nrel0 = n0 - which * C_;
    float* mat = (which == 0) ? g_q : (which == 1) ? g_k : g_v;
#pragma unroll
    for (int mt = 0; mt < 2; mt++) {
        const int m = m0 + wm * 32 + mt * 16 + g;   // and m+8
#pragma unroll
        for (int rr = 0; rr < 2; rr++) {
            const int mr = m + rr * 8;
            const int bb = mr >> 11;
            const int t  = mr & 2047;
#pragma unroll
            for (int nt = 0; nt < 8; nt++) {
                const int nrel = nrel0 + wn * 64 + nt * 8 + 2 * tig;
                const int head = nrel >> 6;
                const int dcol = nrel & 63;
                const float b0 = bias[which * C_ + nrel];
                const float b1 = bias[which * C_ + nrel + 1];
                float2 o;
                o.x = d[mt][nt][2 * rr + 0] + b0;
                o.y = d[mt][nt][2 * rr + 1] + b1;
                *reinterpret_cast<float2*>(
                    mat + (((size_t)bb * NH_ + head) * T_ + t) * HS_ + dcol) = o;
            }
        }
    }
}

// ---------------------------------------------------------------------------
// Kernel: flash-style causal attention (CUDA-core, f32x2), BR=128, BC=64,
// 256 threads, 8x4 register tile, register prefetch of next K/V block.
// ---------------------------------------------------------------------------
constexpr int BR  = 128;
constexpr int BC  = 64;
constexpr int LDA = 68;
constexpr int ATTN_SMEM = (BR + BC + BC + BR) * LDA * (int)sizeof(float); // 104448

__global__ __launch_bounds__(256) void attn_kernel(float* __restrict__ out)
{
    extern __shared__ float sm[];
    float* Qs = sm;                   // [row][d]
    float* Kt = Qs + BR * LDA;        // [d][key]
    float* Vs = Kt + BC * LDA;        // [key][d]
    float* Ps = Vs + BC * LDA;        // [row][key]

    const int tid = threadIdx.x;
    const int qt  = (T_ / BR) - 1 - blockIdx.x;   // heavy tiles first
    const int h   = blockIdx.y;
    const int b   = blockIdx.z;
    const size_t base = ((size_t)b * NH_ + h) * T_ * HS_;

    const int ty = tid >> 4, tx = tid & 15;
    const int row8 = ty * 8, col4 = tx * 4;

    // Q tile load
    {
        const int r  = tid >> 1;
        const int cp = (tid & 1) * 32;
        const float* src = g_q + base + (size_t)(qt * BR + r) * HS_ + cp;
        float* dst = Qs + r * LDA + cp;
#pragma unroll
        for (int i = 0; i < 8; i++)
            reinterpret_cast<float4*>(dst)[i] =
                reinterpret_cast<const float4*>(src)[i];
    }

    float m_i[8], l_i[8];
    ull acc[8][2];
#pragma unroll
    for (int i = 0; i < 8; i++) {
        m_i[i] = -INFINITY; l_i[i] = 0.0f;
        acc[i][0] = 0ULL; acc[i][1] = 0ULL;
    }
    const float scale = 0.125f;

    const int kvr = tid >> 2;          // 0..63
    const int kvc = (tid & 3) * 16;
    float4 kr[4], vr[4];
    {   // prefetch block 0
        const float* ks = g_k + base + (size_t)kvr * HS_ + kvc;
        const float* vs = g_v + base + (size_t)kvr * HS_ + kvc;
#pragma unroll
        for (int i = 0; i < 4; i++) {
            kr[i] = reinterpret_cast<const float4*>(ks)[i];
            vr[i] = reinterpret_cast<const float4*>(vs)[i];
        }
    }

    const int jmax = 2 * qt + 1;
    for (int j = 0; j <= jmax; j++) {
        __syncthreads();               // readers done with previous K/V
        // store prefetched K (transposed) and V
#pragma unroll
        for (int i = 0; i < 4; i++) {
            *reinterpret_cast<float4*>(Vs + kvr * LDA + kvc + 4 * i) = vr[i];
            Kt[(kvc + 4 * i + 0) * LDA + kvr] = kr[i].x;
            Kt[(kvc + 4 * i + 1) * LDA + kvr] = kr[i].y;
            Kt[(kvc + 4 * i + 2) * LDA + kvr] = kr[i].z;
            Kt[(kvc + 4 * i + 3) * LDA + kvr] = kr[i].w;
        }
        if (j < jmax) {                // prefetch next block during compute
            const float* ks = g_k + base + (size_t)((j + 1) * BC + kvr) * HS_ + kvc;
            const float* vs = g_v + base + (size_t)((j + 1) * BC + kvr) * HS_ + kvc;
#pragma unroll
            for (int i = 0; i < 4; i++) {
                kr[i] = reinterpret_cast<const float4*>(ks)[i];
                vr[i] = reinterpret_cast<const float4*>(vs)[i];
            }
        }
        __syncthreads();

        // ---- S = Q K^T : 8x4 register tile ----
        ull sp[8][2];
#pragma unroll
        for (int i = 0; i < 8; i++) { sp[i][0] = 0ULL; sp[i][1] = 0ULL; }

#pragma unroll 2
        for (int d0 = 0; d0 < HS_; d0 += 4) {
            ulonglong2 kb[4];
#pragma unroll
            for (int u = 0; u < 4; u++)
                kb[u] = *reinterpret_cast<const ulonglong2*>(
                    Kt + (d0 + u) * LDA + col4);
#pragma unroll
            for (int hlf = 0; hlf < 2; hlf++) {
                float aq[4][4];
#pragma unroll
                for (int i = 0; i < 4; i++)
                    *reinterpret_cast<float4*>(aq[i]) =
                        *reinterpret_cast<const float4*>(
                            Qs + (row8 + hlf * 4 + i) * LDA + d0);
#pragma unroll
                for (int u = 0; u < 4; u++)
#pragma unroll
                    for (int i = 0; i < 4; i++) {
                        ull aa = dup2(aq[i][u]);
                        fma2(sp[hlf * 4 + i][0], aa, kb[u].x);
                        fma2(sp[hlf * 4 + i][1], aa, kb[u].y);
                    }
            }
        }

        float s[8][4];
#pragma unroll
        for (int i = 0; i < 8; i++) {
            float2 f0 = unpk(sp[i][0]), f1 = unpk(sp[i][1]);
            s[i][0] = f0.x * scale; s[i][1] = f0.y * scale;
            s[i][2] = f1.x * scale; s[i][3] = f1.y * scale;
        }

        if (j >= 2 * qt) {             // diagonal-straddling blocks
            const int koff = j * BC - qt * BR;
#pragma unroll
            for (int i = 0; i < 8; i++)
#pragma unroll
                for (int c = 0; c < 4; c++)
                    if (koff + col4 + c > row8 + i) s[i][c] = -INFINITY;
        }

        // ---- online softmax ----
#pragma unroll
        for (int i = 0; i < 8; i++) {
            float mx = fmaxf(fmaxf(s[i][0], s[i][1]), fmaxf(s[i][2], s[i][3]));
            mx = fmaxf(mx, __shfl_xor_sync(0xffffffffu, mx, 1));
            mx = fmaxf(mx, __shfl_xor_sync(0xffffffffu, mx, 2));
            mx = fmaxf(mx, __shfl_xor_sync(0xffffffffu, mx, 4));
            mx = fmaxf(mx, __shfl_xor_sync(0xffffffffu, mx, 8));
            const float mn   = fmaxf(m_i[i], mx);
            const float corr = __expf(m_i[i] - mn);
            m_i[i] = mn;
            float sum = 0.0f;
#pragma unroll
            for (int c = 0; c < 4; c++) {
                const float p = __expf(s[i][c] - mn);
                s[i][c] = p;
                sum += p;
            }
            sum += __shfl_xor_sync(0xffffffffu, sum, 1);
            sum += __shfl_xor_sync(0xffffffffu, sum, 2);
            sum += __shfl_xor_sync(0xffffffffu, sum, 4);
            sum += __shfl_xor_sync(0xffffffffu, sum, 8);
            l_i[i] = l_i[i] * corr + sum;
            ull cc = dup2(corr);
            mul2(acc[i][0], acc[i][0], cc);
            mul2(acc[i][1], acc[i][1], cc);
            *reinterpret_cast<float4*>(Ps + (row8 + i) * LDA + col4) =
                make_float4(s[i][0], s[i][1], s[i][2], s[i][3]);
        }
        __syncwarp();

        // ---- O += P V : 8x4 register tile ----
#pragma unroll 2
        for (int kl0 = 0; kl0 < BC; kl0 += 4) {
            ulonglong2 vb[4];
#pragma unroll
            for (int u = 0; u < 4; u++)
                vb[u] = *reinterpret_cast<const ulonglong2*>(
                    Vs + (kl0 + u) * LDA + col4);
#pragma unroll
            for (int hlf = 0; hlf < 2; hlf++) {
                float pa[4][4];
#pragma unroll
                for (int i = 0; i < 4; i++)
                    *reinterpret_cast<float4*>(pa[i]) =
                        *reinterpret_cast<const float4*>(
                            Ps + (row8 + hlf * 4 + i) * LDA + kl0);
#pragma unroll
                for (int u = 0; u < 4; u++)
#pragma unroll
                    for (int i = 0; i < 4; i++) {
                        ull aa = dup2(pa[i][u]);
                        fma2(acc[hlf * 4 + i][0], aa, vb[u].x);
                        fma2(acc[hlf * 4 + i][1], aa, vb[u].y);
                    }
            }
        }
    }

    // ---- normalize + write [B, NH, T, HS] ----
#pragma unroll
    for (int i = 0; i < 8; i++) {
        const float inv = 1.0f / l_i[i];
        float2 f0 = unpk(acc[i][0]), f1 = unpk(acc[i][1]);
        float4 o = make_float4(f0.x * inv, f0.y * inv, f1.x * inv, f1.y * inv);
        *reinterpret_cast<float4*>(
            out + base + (size_t)(qt * BR + row8 + i) * HS_ + col4) = o;
    }
}

// ---------------------------------------------------------------------------
extern "C" void kernel_launch(void* const* d_in, const int* in_sizes, int n_in,
                              void* d_out, int out_size)
{
    (void)in_sizes; (void)n_in; (void)out_size;
    const float* x    = (const float*)d_in[0];
    const float* w    = (const float*)d_in[1];
    const float* bias = (const float*)d_in[2];
    float* out = (float*)d_out;

    conv_x_kernel<<<(M_ * K_ / 4 + 255) / 256, 256>>>(x);
    conv_w_kernel<<<((K_ / 4) * N3_ + 255) / 256, 256>>>(w);

    cudaFuncSetAttribute(qkv_gemm_tc,
                         cudaFuncAttributeMaxDynamicSharedMemorySize, GEMM_SMEM);
    dim3 g1(N3_ / 128, M_ / 128);    // (18, 32)
    qkv_gemm_tc<<<g1, 256, GEMM_SMEM>>>(bias);

    cudaFuncSetAttribute(attn_kernel,
                         cudaFuncAttributeMaxDynamicSharedMemorySize, ATTN_SMEM);
    dim3 g2(T_ / BR, NH_, B_);       // (16, 12, 2)
    attn_kernel<<<g2, 256, ATTN_SMEM>>>(out);
}

// round 10
// speedup vs baseline: 2.1194x; 1.6784x over previous
#include <cuda_runtime.h>
#include <cuda_bf16.h>
#include <math.h>
#include <stdint.h>

// Problem constants
constexpr int B_  = 2;
constexpr int T_  = 2048;
constexpr int C_  = 768;
constexpr int NH_ = 12;
constexpr int HS_ = 64;
constexpr int M_  = B_ * T_;      // 4096
constexpr int N3_ = 3 * C_;       // 2304
constexpr int K_  = C_;           // 768

typedef unsigned long long ull;

// ---------------------------------------------------------------------------
// PTX helpers (base-PTX only: legal at compute_103)
// ---------------------------------------------------------------------------
__device__ __forceinline__ uint32_t smem_u32(const void* p) {
    uint32_t a;
    asm("{ .reg .u64 t; cvta.to.shared.u64 t, %1; cvt.u32.u64 %0, t; }"
        : "=r"(a) : "l"(p));
    return a;
}

#define LDSM4(r0, r1, r2, r3, addr)                                          \
    asm volatile("ldmatrix.sync.aligned.m8n8.x4.shared.b16 {%0,%1,%2,%3}, [%4];" \
                 : "=r"(r0), "=r"(r1), "=r"(r2), "=r"(r3) : "r"(addr))

#define LDSM4T(r0, r1, r2, r3, addr)                                         \
    asm volatile("ldmatrix.sync.aligned.m8n8.x4.trans.shared.b16 {%0,%1,%2,%3}, [%4];" \
                 : "=r"(r0), "=r"(r1), "=r"(r2), "=r"(r3) : "r"(addr))

#define MMA16816(d, a, b0v, b1v)                                             \
    asm volatile("mma.sync.aligned.m16n8k16.row.col.f32.bf16.bf16.f32 "      \
                 "{%0,%1,%2,%3}, {%4,%5,%6,%7}, {%8,%9}, {%0,%1,%2,%3};"     \
                 : "+f"((d)[0]), "+f"((d)[1]), "+f"((d)[2]), "+f"((d)[3])    \
                 : "r"((a)[0]), "r"((a)[1]), "r"((a)[2]), "r"((a)[3]),       \
                   "r"(b0v), "r"(b1v))

#define CP_ASYNC16(dst, src)                                                 \
    asm volatile("cp.async.cg.shared.global [%0], [%1], 16;"                 \
                 :: "r"(dst), "l"(src) : "memory")
#define CP_COMMIT() asm volatile("cp.async.commit_group;" ::: "memory")
#define CP_WAIT0()  asm volatile("cp.async.wait_group 0;" ::: "memory")
#define CP_WAIT1()  asm volatile("cp.async.wait_group 1;" ::: "memory")

// pack two f32 into bf16x2 (x -> low half, y -> high half), return residuals
__device__ __forceinline__ uint32_t pack_bf2(float x, float y) {
    uint32_t hp;
    asm("cvt.rn.bf16x2.f32 %0, %1, %2;" : "=r"(hp) : "f"(y), "f"(x));
    return hp;
}
__device__ __forceinline__ uint32_t pack_split(float x, float y, uint32_t& lo) {
    const uint32_t hp = pack_bf2(x, y);
    const float hx = __uint_as_float(hp << 16);
    const float hy = __uint_as_float(hp & 0xffff0000u);
    lo = pack_bf2(x - hx, y - hy);
    return hp;
}

// ---------------------------------------------------------------------------
// Device scratch (all bf16)
// ---------------------------------------------------------------------------
constexpr size_t QKV_ELEMS = (size_t)B_ * NH_ * T_ * HS_;
__device__ __nv_bfloat16 g_qh[QKV_ELEMS];   // Q pre-scaled by 0.125
__device__ __nv_bfloat16 g_ql[QKV_ELEMS];
__device__ __nv_bfloat16 g_kh[QKV_ELEMS];
__device__ __nv_bfloat16 g_kl[QKV_ELEMS];
__device__ __nv_bfloat16 g_vh[QKV_ELEMS];
__device__ __nv_bfloat16 g_vl[QKV_ELEMS];
__device__ __nv_bfloat16 g_xh[(size_t)M_ * K_];
__device__ __nv_bfloat16 g_xl[(size_t)M_ * K_];
__device__ __nv_bfloat16 g_wth[(size_t)N3_ * K_];   // w transposed [N][K]
__device__ __nv_bfloat16 g_wtl[(size_t)N3_ * K_];

// ---------------------------------------------------------------------------
// Convert kernels: fp32 -> bf16 hi/lo split (+ transpose for w)
// ---------------------------------------------------------------------------
__global__ __launch_bounds__(256) void conv_x_kernel(const float* __restrict__ x)
{
    const int idx = blockIdx.x * 256 + threadIdx.x;
    if (idx >= M_ * K_ / 4) return;
    float4 v = reinterpret_cast<const float4*>(x)[idx];
    float vv[4] = {v.x, v.y, v.z, v.w};
    ushort hs[4], ls[4];
#pragma unroll
    for (int e = 0; e < 4; e++) {
        __nv_bfloat16 h = __float2bfloat16(vv[e]);
        __nv_bfloat16 l = __float2bfloat16(vv[e] - __bfloat162float(h));
        hs[e] = __bfloat16_as_ushort(h);
        ls[e] = __bfloat16_as_ushort(l);
    }
    *reinterpret_cast<ushort4*>(&g_xh[(size_t)idx * 4]) =
        make_ushort4(hs[0], hs[1], hs[2], hs[3]);
    *reinterpret_cast<ushort4*>(&g_xl[(size_t)idx * 4]) =
        make_ushort4(ls[0], ls[1], ls[2], ls[3]);
}

__global__ __launch_bounds__(256) void conv_w_kernel(const float* __restrict__ w)
{
    const int idx = blockIdx.x * 256 + threadIdx.x;
    if (idx >= (K_ / 4) * N3_) return;
    const int n  = idx % N3_;
    const int k4 = idx / N3_;
    ushort hs[4], ls[4];
#pragma unroll
    for (int e = 0; e < 4; e++) {
        float v = w[(size_t)(4 * k4 + e) * N3_ + n];
        __nv_bfloat16 h = __float2bfloat16(v);
        __nv_bfloat16 l = __float2bfloat16(v - __bfloat162float(h));
        hs[e] = __bfloat16_as_ushort(h);
        ls[e] = __bfloat16_as_ushort(l);
    }
    *reinterpret_cast<ushort4*>(&g_wth[(size_t)n * K_ + 4 * k4]) =
        make_ushort4(hs[0], hs[1], hs[2], hs[3]);
    *reinterpret_cast<ushort4*>(&g_wtl[(size_t)n * K_ + 4 * k4]) =
        make_ushort4(ls[0], ls[1], ls[2], ls[3]);
}

// ---------------------------------------------------------------------------
// Kernel: HMMA 3-term split GEMM, epilogue emits bf16 hi/lo Q(K)(V).
// CTA tile M=128 x N=128, 256 threads (8 warps, warp tile 32x64).
// ---------------------------------------------------------------------------
constexpr int CH  = 32;
constexpr int LDK = 40;
constexpr int NCH = K_ / CH;          // 24
constexpr int ARR_BYTES = 128 * LDK * 2;
constexpr int BUF_BYTES = 4 * ARR_BYTES;
constexpr int OFF_AH = 0;
constexpr int OFF_AL = ARR_BYTES;
constexpr int OFF_BH = 2 * ARR_BYTES;
constexpr int OFF_BL = 3 * ARR_BYTES;
constexpr int GEMM_SMEM = 2 * BUF_BYTES;          // 81920

__global__ __launch_bounds__(256, 1) void qkv_gemm_tc(const float* __restrict__ bias)
{
    extern __shared__ char smem[];
    const uint32_t sb = smem_u32(smem);
    const int tid  = threadIdx.x;
    const int wid  = tid >> 5, lane = tid & 31;
    const int wm   = wid & 3;
    const int wn   = wid >> 2;
    const int m0   = blockIdx.y * 128;
    const int n0   = blockIdx.x * 128;

    const int grow = tid >> 1;
    const int gpart = tid & 1;
    const __nv_bfloat16* xh = g_xh + (size_t)(m0 + grow) * K_ + gpart * 16;
    const __nv_bfloat16* xl = g_xl + (size_t)(m0 + grow) * K_ + gpart * 16;
    const __nv_bfloat16* bh = g_wth + (size_t)(n0 + grow) * K_ + gpart * 16;
    const __nv_bfloat16* bl = g_wtl + (size_t)(n0 + grow) * K_ + gpart * 16;
    const uint32_t sdst = sb + (uint32_t)((grow * LDK + gpart * 16) * 2);

    auto issue_loads = [&](int c, int buf) {
        const uint32_t d0 = sdst + buf * BUF_BYTES;
        const int ko = c * CH;
#pragma unroll
        for (int i = 0; i < 2; i++) {
            CP_ASYNC16(d0 + OFF_AH + i * 16, xh + ko + i * 8);
            CP_ASYNC16(d0 + OFF_AL + i * 16, xl + ko + i * 8);
            CP_ASYNC16(d0 + OFF_BH + i * 16, bh + ko + i * 8);
            CP_ASYNC16(d0 + OFF_BL + i * 16, bl + ko + i * 8);
        }
    };

    const int t4 = lane >> 3, r8 = lane & 7;
    const int a_moff = (t4 & 1) * 8, a_koff = (t4 >> 1) * 8;
    const int b_noff = (t4 >> 1) * 8, b_koff = (t4 & 1) * 8;

    float d[2][8][4];
#pragma unroll
    for (int mt = 0; mt < 2; mt++)
#pragma unroll
        for (int nt = 0; nt < 8; nt++)
#pragma unroll
            for (int e = 0; e < 4; e++) d[mt][nt][e] = 0.0f;

    issue_loads(0, 0);
    CP_COMMIT();

    for (int c = 0; c < NCH; c++) {
        CP_WAIT0();
        __syncthreads();
        if (c + 1 < NCH) { issue_loads(c + 1, (c + 1) & 1); }
        CP_COMMIT();

        const uint32_t bufb = sb + (uint32_t)((c & 1) * BUF_BYTES);
#pragma unroll
        for (int ks = 0; ks < 2; ks++) {
            uint32_t ah[2][4], al[2][4];
#pragma unroll
            for (int mt = 0; mt < 2; mt++) {
                const uint32_t ad = bufb + OFF_AH +
                    (uint32_t)(((wm * 32 + mt * 16 + a_moff + r8) * LDK +
                                ks * 16 + a_koff) * 2);
                LDSM4(ah[mt][0], ah[mt][1], ah[mt][2], ah[mt][3], ad);
                LDSM4(al[mt][0], al[mt][1], al[mt][2], al[mt][3],
                      ad + (OFF_AL - OFF_AH));
            }
            uint32_t bhf[4][4], blf[4][4];
#pragma unroll
            for (int np = 0; np < 4; np++) {
                const uint32_t bd = bufb + OFF_BH +
                    (uint32_t)(((wn * 64 + np * 16 + b_noff + r8) * LDK +
                                ks * 16 + b_koff) * 2);
                LDSM4(bhf[np][0], bhf[np][1], bhf[np][2], bhf[np][3], bd);
                LDSM4(blf[np][0], blf[np][1], blf[np][2], blf[np][3],
                      bd + (OFF_BL - OFF_BH));
            }
#pragma unroll
            for (int mt = 0; mt < 2; mt++)
#pragma unroll
                for (int nt = 0; nt < 8; nt++) {
                    const int np = nt >> 1, hf = (nt & 1) * 2;
                    MMA16816(d[mt][nt], ah[mt], bhf[np][hf], bhf[np][hf + 1]);
                    MMA16816(d[mt][nt], ah[mt], blf[np][hf], blf[np][hf + 1]);
                    MMA16816(d[mt][nt], al[mt], bhf[np][hf], bhf[np][hf + 1]);
                }
        }
    }

    // Epilogue: bias (+q scale), bf16 hi/lo split, scatter to [B, NH, T, HS]
    const int g = lane >> 2, tig = lane & 3;
    const int which = n0 / C_;
    const int nrel0 = n0 - which * C_;
    const float qscale = (which == 0) ? 0.125f : 1.0f;
    __nv_bfloat16* mh = (which == 0) ? g_qh : (which == 1) ? g_kh : g_vh;
    __nv_bfloat16* ml = (which == 0) ? g_ql : (which == 1) ? g_kl : g_vl;
#pragma unroll
    for (int mt = 0; mt < 2; mt++) {
        const int m = m0 + wm * 32 + mt * 16 + g;
#pragma unroll
        for (int rr = 0; rr < 2; rr++) {
            const int mr = m + rr * 8;
            const int bb = mr >> 11;
            const int t  = mr & 2047;
#pragma unroll
            for (int nt = 0; nt < 8; nt++) {
                const int nrel = nrel0 + wn * 64 + nt * 8 + 2 * tig;
                const int head = nrel >> 6;
                const int dcol = nrel & 63;
                const float v0 =
                    (d[mt][nt][2 * rr + 0] + bias[which * C_ + nrel]) * qscale;
                const float v1 =
                    (d[mt][nt][2 * rr + 1] + bias[which * C_ + nrel + 1]) * qscale;
                uint32_t lp;
                const uint32_t hp = pack_split(v0, v1, lp);
                const size_t idx = (((size_t)bb * NH_ + head) * T_ + t) * HS_ + dcol;
                *reinterpret_cast<uint32_t*>(mh + idx) = hp;
                *reinterpret_cast<uint32_t*>(ml + idx) = lp;
            }
        }
    }
}

// ---------------------------------------------------------------------------
// Kernel: tensor-core flash attention.
// CTA = (b, h, 64-row q-tile), 128 threads (4 warps x m16). BC=64 keys.
// S = QK^T 3-term bf16 split; softmax on fragments; P in registers (split);
// O += P V 3-term with ldmatrix.trans for V. cp.async double-buffered K/V.
// ---------------------------------------------------------------------------
constexpr int A_LDH   = 72;                          // halves per smem row
constexpr int A_ARR   = 64 * A_LDH * 2;              // 9216 B per 64x64 tile
constexpr int A_OFF_QH = 0;
constexpr int A_OFF_QL = A_ARR;
constexpr int A_STAGE0 = 2 * A_ARR;                  // 18432
constexpr int A_KH = 0, A_KL = A_ARR, A_VH = 2 * A_ARR, A_VL = 3 * A_ARR;
constexpr int A_STAGEB = 4 * A_ARR;                  // 36864
constexpr int ATTN_SMEM = A_STAGE0 + 2 * A_STAGEB;   // 92160

__global__ __launch_bounds__(128) void attn_tc(float* __restrict__ out)
{
    extern __shared__ char smc[];
    const uint32_t sb = smem_u32(smc);
    const int tid  = threadIdx.x;
    const int wid  = tid >> 5, lane = tid & 31;
    const int g    = lane >> 2, t = lane & 3;
    const int t4   = lane >> 3, r8 = lane & 7;
    const int qt   = (T_ / 64) - 1 - blockIdx.x;     // heavy tiles first
    const int h    = blockIdx.y;
    const int b    = blockIdx.z;
    const size_t base = ((size_t)b * NH_ + h) * T_ * HS_;

    // ---- async load helpers: thread -> (row = tid/2, 32-half chunk = tid&1)
    const int lrow = tid >> 1;
    const int lcol = (tid & 1) * 32;
    const uint32_t sdst = (uint32_t)((lrow * A_LDH + lcol) * 2);

    {   // Q (hi/lo) for this q-tile
        const __nv_bfloat16* qh = g_qh + base + (size_t)(qt * 64 + lrow) * HS_ + lcol;
        const __nv_bfloat16* ql = g_ql + base + (size_t)(qt * 64 + lrow) * HS_ + lcol;
#pragma unroll
        for (int i = 0; i < 4; i++) {
            CP_ASYNC16(sb + A_OFF_QH + sdst + i * 16, qh + i * 8);
            CP_ASYNC16(sb + A_OFF_QL + sdst + i * 16, ql + i * 8);
        }
    }
    auto issue_kv = [&](int j, int s) {
        const uint32_t st = sb + A_STAGE0 + s * A_STAGEB;
        const size_t src = base + (size_t)(j * 64 + lrow) * HS_ + lcol;
#pragma unroll
        for (int i = 0; i < 4; i++) {
            CP_ASYNC16(st + A_KH + sdst + i * 16, g_kh + src + i * 8);
            CP_ASYNC16(st + A_KL + sdst + i * 16, g_kl + src + i * 8);
            CP_ASYNC16(st + A_VH + sdst + i * 16, g_vh + src + i * 8);
            CP_ASYNC16(st + A_VL + sdst + i * 16, g_vl + src + i * 8);
        }
    };
    issue_kv(0, 0);
    CP_COMMIT();

    // fragment geometry
    const int a_moff = (t4 & 1) * 8, a_koff = (t4 >> 1) * 8;
    const int b_noff = (t4 >> 1) * 8, b_koff = (t4 & 1) * 8;

    float o[8][4];
#pragma unroll
    for (int nt = 0; nt < 8; nt++)
#pragma unroll
        for (int e = 0; e < 4; e++) o[nt][e] = 0.0f;
    float m_i[2] = {-INFINITY, -INFINITY};
    float l_i[2] = {0.0f, 0.0f};

    uint32_t qhf[4][4], qlf[4][4];
    bool qloaded = false;

    for (int j = 0; j <= qt; j++) {
        if (j < qt) { issue_kv(j + 1, (j + 1) & 1); CP_COMMIT(); }
        if (j < qt) { CP_WAIT1(); } else { CP_WAIT0(); }
        __syncthreads();

        if (!qloaded) {
            qloaded = true;
#pragma unroll
            for (int ks = 0; ks < 4; ks++) {
                const uint32_t qa = sb + A_OFF_QH +
                    (uint32_t)(((wid * 16 + a_moff + r8) * A_LDH +
                                ks * 16 + a_koff) * 2);
                LDSM4(qhf[ks][0], qhf[ks][1], qhf[ks][2], qhf[ks][3], qa);
                LDSM4(qlf[ks][0], qlf[ks][1], qlf[ks][2], qlf[ks][3],
                      qa + (A_OFF_QL - A_OFF_QH));
            }
        }

        const uint32_t st = sb + A_STAGE0 + (j & 1) * A_STAGEB;

        // ---- S = Q K^T (3-term split) ----
        float s[8][4];
#pragma unroll
        for (int nt = 0; nt < 8; nt++)
#pragma unroll
            for (int e = 0; e < 4; e++) s[nt][e] = 0.0f;

#pragma unroll
        for (int ks = 0; ks < 4; ks++) {
#pragma unroll
            for (int np = 0; np < 4; np++) {
                const uint32_t ka = st + A_KH +
                    (uint32_t)(((np * 16 + b_noff + r8) * A_LDH +
                                ks * 16 + b_koff) * 2);
                uint32_t kh[4], kl[4];
                LDSM4(kh[0], kh[1], kh[2], kh[3], ka);
                LDSM4(kl[0], kl[1], kl[2], kl[3], ka + (A_KL - A_KH));
#pragma unroll
                for (int half = 0; half < 2; half++) {
                    const int nt = np * 2 + half, hf = half * 2;
                    MMA16816(s[nt], qhf[ks], kh[hf], kh[hf + 1]);
                    MMA16816(s[nt], qhf[ks], kl[hf], kl[hf + 1]);
                    MMA16816(s[nt], qlf[ks], kh[hf], kh[hf + 1]);
                }
            }
        }

        // ---- causal mask on diagonal block ----
        if (j == qt) {
            const int r0 = wid * 16 + g;
#pragma unroll
            for (int nt = 0; nt < 8; nt++) {
                const int c0 = nt * 8 + 2 * t;
                if (c0 > r0)          s[nt][0] = -INFINITY;
                if (c0 + 1 > r0)      s[nt][1] = -INFINITY;
                if (c0 > r0 + 8)      s[nt][2] = -INFINITY;
                if (c0 + 1 > r0 + 8)  s[nt][3] = -INFINITY;
            }
        }

        // ---- online softmax on fragments (rows g, g+8) ----
        float mx0 = -INFINITY, mx1 = -INFINITY;
#pragma unroll
        for (int nt = 0; nt < 8; nt++) {
            mx0 = fmaxf(mx0, fmaxf(s[nt][0], s[nt][1]));
            mx1 = fmaxf(mx1, fmaxf(s[nt][2], s[nt][3]));
        }
        mx0 = fmaxf(mx0, __shfl_xor_sync(0xffffffffu, mx0, 1));
        mx0 = fmaxf(mx0, __shfl_xor_sync(0xffffffffu, mx0, 2));
        mx1 = fmaxf(mx1, __shfl_xor_sync(0xffffffffu, mx1, 1));
        mx1 = fmaxf(mx1, __shfl_xor_sync(0xffffffffu, mx1, 2));
        const float mn0 = fmaxf(m_i[0], mx0);
        const float mn1 = fmaxf(m_i[1], mx1);
        const float corr0 = __expf(m_i[0] - mn0);
        const float corr1 = __expf(m_i[1] - mn1);
        m_i[0] = mn0; m_i[1] = mn1;

        float sum0 = 0.0f, sum1 = 0.0f;
#pragma unroll
        for (int nt = 0; nt < 8; nt++) {
            s[nt][0] = __expf(s[nt][0] - mn0); sum0 += s[nt][0];
            s[nt][1] = __expf(s[nt][1] - mn0); sum0 += s[nt][1];
            s[nt][2] = __expf(s[nt][2] - mn1); sum1 += s[nt][2];
            s[nt][3] = __expf(s[nt][3] - mn1); sum1 += s[nt][3];
            o[nt][0] *= corr0; o[nt][1] *= corr0;
            o[nt][2] *= corr1; o[nt][3] *= corr1;
        }
        sum0 += __shfl_xor_sync(0xffffffffu, sum0, 1);
        sum0 += __shfl_xor_sync(0xffffffffu, sum0, 2);
        sum1 += __shfl_xor_sync(0xffffffffu, sum1, 1);
        sum1 += __shfl_xor_sync(0xffffffffu, sum1, 2);
        l_i[0] = l_i[0] * corr0 + sum0;
        l_i[1] = l_i[1] * corr1 + sum1;

        // ---- P -> A fragments (bf16 hi/lo split, in registers) ----
        uint32_t ph[4][4], pl[4][4];
#pragma unroll
        for (int ks = 0; ks < 4; ks++) {
            ph[ks][0] = pack_split(s[2 * ks][0],     s[2 * ks][1],     pl[ks][0]);
            ph[ks][1] = pack_split(s[2 * ks][2],     s[2 * ks][3],     pl[ks][1]);
            ph[ks][2] = pack_split(s[2 * ks + 1][0], s[2 * ks + 1][1], pl[ks][2]);
            ph[ks][3] = pack_split(s[2 * ks + 1][2], s[2 * ks + 1][3], pl[ks][3]);
        }

        // ---- O += P V (3-term split), V via ldmatrix.trans ----
#pragma unroll
        for (int ks = 0; ks < 4; ks++) {
#pragma unroll
            for (int dp = 0; dp < 4; dp++) {
                const uint32_t va = st + A_VH +
                    (uint32_t)(((ks * 16 + (t4 & 1) * 8 + r8) * A_LDH +
                                dp * 16 + (t4 >> 1) * 8) * 2);
                uint32_t vh[4], vl[4];
                LDSM4T(vh[0], vh[1], vh[2], vh[3], va);
                LDSM4T(vl[0], vl[1], vl[2], vl[3], va + (A_VL - A_VH));
#pragma unroll
                for (int half = 0; half < 2; half++) {
                    const int nt = dp * 2 + half, hf = half * 2;
                    MMA16816(o[nt], ph[ks], vh[hf], vh[hf + 1]);
                    MMA16816(o[nt], ph[ks], vl[hf], vl[hf + 1]);
                    MMA16816(o[nt], pl[ks], vh[hf], vh[hf + 1]);
                }
            }
        }
        __syncthreads();   // all warps done with this stage before re-fill
    }

    // ---- normalize + write [B, NH, T, HS] ----
    const float inv0 = 1.0f / l_i[0];
    const float inv1 = 1.0f / l_i[1];
    const int r0 = qt * 64 + wid * 16 + g;
#pragma unroll
    for (int nt = 0; nt < 8; nt++) {
        const int col = nt * 8 + 2 * t;
        *reinterpret_cast<float2*>(out + base + (size_t)r0 * HS_ + col) =
            make_float2(o[nt][0] * inv0, o[nt][1] * inv0);
        *reinterpret_cast<float2*>(out + base + (size_t)(r0 + 8) * HS_ + col) =
            make_float2(o[nt][2] * inv1, o[nt][3] * inv1);
    }
}

// ---------------------------------------------------------------------------
extern "C" void kernel_launch(void* const* d_in, const int* in_sizes, int n_in,
                              void* d_out, int out_size)
{
    (void)in_sizes; (void)n_in; (void)out_size;
    const float* x    = (const float*)d_in[0];
    const float* w    = (const float*)d_in[1];
    const float* bias = (const float*)d_in[2];
    float* out = (float*)d_out;

    conv_x_kernel<<<(M_ * K_ / 4 + 255) / 256, 256>>>(x);
    conv_w_kernel<<<((K_ / 4) * N3_ + 255) / 256, 256>>>(w);

    cudaFuncSetAttribute(qkv_gemm_tc,
                         cudaFuncAttributeMaxDynamicSharedMemorySize, GEMM_SMEM);
    dim3 g1(N3_ / 128, M_ / 128);    // (18, 32)
    qkv_gemm_tc<<<g1, 256, GEMM_SMEM>>>(bias);

    cudaFuncSetAttribute(attn_tc,
                         cudaFuncAttributeMaxDynamicSharedMemorySize, ATTN_SMEM);
    dim3 g2(T_ / 64, NH_, B_);       // (32, 12, 2)
    attn_tc<<<g2, 128, ATTN_SMEM>>>(out);
}

// round 11
// speedup vs baseline: 2.2406x; 1.0572x over previous
#include <cuda_runtime.h>
#include <cuda_bf16.h>
#include <math.h>
#include <stdint.h>

// Problem constants
constexpr int B_  = 2;
constexpr int T_  = 2048;
constexpr int C_  = 768;
constexpr int NH_ = 12;
constexpr int HS_ = 64;
constexpr int M_  = B_ * T_;      // 4096
constexpr int N3_ = 3 * C_;       // 2304
constexpr int K_  = C_;           // 768

typedef unsigned long long ull;

// ---------------------------------------------------------------------------
// PTX helpers (base-PTX only: legal at compute_103)
// ---------------------------------------------------------------------------
__device__ __forceinline__ uint32_t smem_u32(const void* p) {
    uint32_t a;
    asm("{ .reg .u64 t; cvta.to.shared.u64 t, %1; cvt.u32.u64 %0, t; }"
        : "=r"(a) : "l"(p));
    return a;
}

#define LDSM4(r0, r1, r2, r3, addr)                                          \
    asm volatile("ldmatrix.sync.aligned.m8n8.x4.shared.b16 {%0,%1,%2,%3}, [%4];" \
                 : "=r"(r0), "=r"(r1), "=r"(r2), "=r"(r3) : "r"(addr))

#define LDSM4T(r0, r1, r2, r3, addr)                                         \
    asm volatile("ldmatrix.sync.aligned.m8n8.x4.trans.shared.b16 {%0,%1,%2,%3}, [%4];" \
                 : "=r"(r0), "=r"(r1), "=r"(r2), "=r"(r3) : "r"(addr))

#define MMA16816(d, a, b0v, b1v)                                             \
    asm volatile("mma.sync.aligned.m16n8k16.row.col.f32.bf16.bf16.f32 "      \
                 "{%0,%1,%2,%3}, {%4,%5,%6,%7}, {%8,%9}, {%0,%1,%2,%3};"     \
                 : "+f"((d)[0]), "+f"((d)[1]), "+f"((d)[2]), "+f"((d)[3])    \
                 : "r"((a)[0]), "r"((a)[1]), "r"((a)[2]), "r"((a)[3]),       \
                   "r"(b0v), "r"(b1v))

#define CP_ASYNC16(dst, src)                                                 \
    asm volatile("cp.async.cg.shared.global [%0], [%1], 16;"                 \
                 :: "r"(dst), "l"(src) : "memory")
#define CP_COMMIT() asm volatile("cp.async.commit_group;" ::: "memory")
#define CP_WAIT0()  asm volatile("cp.async.wait_group 0;" ::: "memory")
#define CP_WAIT1()  asm volatile("cp.async.wait_group 1;" ::: "memory")

// fast 2^x
__device__ __forceinline__ float ex2(float x) {
    float y; asm("ex2.approx.ftz.f32 %0, %1;" : "=f"(y) : "f"(x)); return y;
}

// pack two f32 into bf16x2 (x -> low half, y -> high half), return residuals
__device__ __forceinline__ uint32_t pack_bf2(float x, float y) {
    uint32_t hp;
    asm("cvt.rn.bf16x2.f32 %0, %1, %2;" : "=r"(hp) : "f"(y), "f"(x));
    return hp;
}
__device__ __forceinline__ uint32_t pack_split(float x, float y, uint32_t& lo) {
    const uint32_t hp = pack_bf2(x, y);
    const float hx = __uint_as_float(hp << 16);
    const float hy = __uint_as_float(hp & 0xffff0000u);
    lo = pack_bf2(x - hx, y - hy);
    return hp;
}

// ---------------------------------------------------------------------------
// Device scratch (all bf16)
// ---------------------------------------------------------------------------
constexpr size_t QKV_ELEMS = (size_t)B_ * NH_ * T_ * HS_;
__device__ __nv_bfloat16 g_qh[QKV_ELEMS];   // Q pre-scaled by 0.125*log2(e)
__device__ __nv_bfloat16 g_ql[QKV_ELEMS];
__device__ __nv_bfloat16 g_kh[QKV_ELEMS];
__device__ __nv_bfloat16 g_kl[QKV_ELEMS];
__device__ __nv_bfloat16 g_vh[QKV_ELEMS];
__device__ __nv_bfloat16 g_vl[QKV_ELEMS];
__device__ __nv_bfloat16 g_xh[(size_t)M_ * K_];
__device__ __nv_bfloat16 g_xl[(size_t)M_ * K_];
__device__ __nv_bfloat16 g_wth[(size_t)N3_ * K_];   // w transposed [N][K]
__device__ __nv_bfloat16 g_wtl[(size_t)N3_ * K_];

// ---------------------------------------------------------------------------
// Convert kernels: fp32 -> bf16 hi/lo split (+ transpose for w)
// ---------------------------------------------------------------------------
__global__ __launch_bounds__(256) void conv_x_kernel(const float* __restrict__ x)
{
    const int idx = blockIdx.x * 256 + threadIdx.x;
    if (idx >= M_ * K_ / 4) return;
    float4 v = reinterpret_cast<const float4*>(x)[idx];
    float vv[4] = {v.x, v.y, v.z, v.w};
    ushort hs[4], ls[4];
#pragma unroll
    for (int e = 0; e < 4; e++) {
        __nv_bfloat16 h = __float2bfloat16(vv[e]);
        __nv_bfloat16 l = __float2bfloat16(vv[e] - __bfloat162float(h));
        hs[e] = __bfloat16_as_ushort(h);
        ls[e] = __bfloat16_as_ushort(l);
    }
    *reinterpret_cast<ushort4*>(&g_xh[(size_t)idx * 4]) =
        make_ushort4(hs[0], hs[1], hs[2], hs[3]);
    *reinterpret_cast<ushort4*>(&g_xl[(size_t)idx * 4]) =
        make_ushort4(ls[0], ls[1], ls[2], ls[3]);
}

__global__ __launch_bounds__(256) void conv_w_kernel(const float* __restrict__ w)
{
    const int idx = blockIdx.x * 256 + threadIdx.x;
    if (idx >= (K_ / 4) * N3_) return;
    const int n  = idx % N3_;
    const int k4 = idx / N3_;
    ushort hs[4], ls[4];
#pragma unroll
    for (int e = 0; e < 4; e++) {
        float v = w[(size_t)(4 * k4 + e) * N3_ + n];
        __nv_bfloat16 h = __float2bfloat16(v);
        __nv_bfloat16 l = __float2bfloat16(v - __bfloat162float(h));
        hs[e] = __bfloat16_as_ushort(h);
        ls[e] = __bfloat16_as_ushort(l);
    }
    *reinterpret_cast<ushort4*>(&g_wth[(size_t)n * K_ + 4 * k4]) =
        make_ushort4(hs[0], hs[1], hs[2], hs[3]);
    *reinterpret_cast<ushort4*>(&g_wtl[(size_t)n * K_ + 4 * k4]) =
        make_ushort4(ls[0], ls[1], ls[2], ls[3]);
}

// ---------------------------------------------------------------------------
// Kernel: HMMA 3-term split GEMM, epilogue emits bf16 hi/lo Q(K)(V).
// CTA tile M=128 x N=128, 256 threads (8 warps, warp tile 32x64).
// ---------------------------------------------------------------------------
constexpr int CH  = 32;
constexpr int LDK = 40;
constexpr int NCH = K_ / CH;          // 24
constexpr int ARR_BYTES = 128 * LDK * 2;
constexpr int BUF_BYTES = 4 * ARR_BYTES;
constexpr int OFF_AH = 0;
constexpr int OFF_AL = ARR_BYTES;
constexpr int OFF_BH = 2 * ARR_BYTES;
constexpr int OFF_BL = 3 * ARR_BYTES;
constexpr int GEMM_SMEM = 2 * BUF_BYTES;          // 81920

__global__ __launch_bounds__(256, 1) void qkv_gemm_tc(const float* __restrict__ bias)
{
    extern __shared__ char smem[];
    const uint32_t sb = smem_u32(smem);
    const int tid  = threadIdx.x;
    const int wid  = tid >> 5, lane = tid & 31;
    const int wm   = wid & 3;
    const int wn   = wid >> 2;
    const int m0   = blockIdx.y * 128;
    const int n0   = blockIdx.x * 128;

    const int grow = tid >> 1;
    const int gpart = tid & 1;
    const __nv_bfloat16* xh = g_xh + (size_t)(m0 + grow) * K_ + gpart * 16;
    const __nv_bfloat16* xl = g_xl + (size_t)(m0 + grow) * K_ + gpart * 16;
    const __nv_bfloat16* bh = g_wth + (size_t)(n0 + grow) * K_ + gpart * 16;
    const __nv_bfloat16* bl = g_wtl + (size_t)(n0 + grow) * K_ + gpart * 16;
    const uint32_t sdst = sb + (uint32_t)((grow * LDK + gpart * 16) * 2);

    auto issue_loads = [&](int c, int buf) {
        const uint32_t d0 = sdst + buf * BUF_BYTES;
        const int ko = c * CH;
#pragma unroll
        for (int i = 0; i < 2; i++) {
            CP_ASYNC16(d0 + OFF_AH + i * 16, xh + ko + i * 8);
            CP_ASYNC16(d0 + OFF_AL + i * 16, xl + ko + i * 8);
            CP_ASYNC16(d0 + OFF_BH + i * 16, bh + ko + i * 8);
            CP_ASYNC16(d0 + OFF_BL + i * 16, bl + ko + i * 8);
        }
    };

    const int t4 = lane >> 3, r8 = lane & 7;
    const int a_moff = (t4 & 1) * 8, a_koff = (t4 >> 1) * 8;
    const int b_noff = (t4 >> 1) * 8, b_koff = (t4 & 1) * 8;

    float d[2][8][4];
#pragma unroll
    for (int mt = 0; mt < 2; mt++)
#pragma unroll
        for (int nt = 0; nt < 8; nt++)
#pragma unroll
            for (int e = 0; e < 4; e++) d[mt][nt][e] = 0.0f;

    issue_loads(0, 0);
    CP_COMMIT();

    for (int c = 0; c < NCH; c++) {
        CP_WAIT0();
        __syncthreads();
        if (c + 1 < NCH) { issue_loads(c + 1, (c + 1) & 1); }
        CP_COMMIT();

        const uint32_t bufb = sb + (uint32_t)((c & 1) * BUF_BYTES);
#pragma unroll
        for (int ks = 0; ks < 2; ks++) {
            uint32_t ah[2][4], al[2][4];
#pragma unroll
            for (int mt = 0; mt < 2; mt++) {
                const uint32_t ad = bufb + OFF_AH +
                    (uint32_t)(((wm * 32 + mt * 16 + a_moff + r8) * LDK +
                                ks * 16 + a_koff) * 2);
                LDSM4(ah[mt][0], ah[mt][1], ah[mt][2], ah[mt][3], ad);
                LDSM4(al[mt][0], al[mt][1], al[mt][2], al[mt][3],
                      ad + (OFF_AL - OFF_AH));
            }
            uint32_t bhf[4][4], blf[4][4];
#pragma unroll
            for (int np = 0; np < 4; np++) {
                const uint32_t bd = bufb + OFF_BH +
                    (uint32_t)(((wn * 64 + np * 16 + b_noff + r8) * LDK +
                                ks * 16 + b_koff) * 2);
                LDSM4(bhf[np][0], bhf[np][1], bhf[np][2], bhf[np][3], bd);
                LDSM4(blf[np][0], blf[np][1], blf[np][2], blf[np][3],
                      bd + (OFF_BL - OFF_BH));
            }
#pragma unroll
            for (int mt = 0; mt < 2; mt++)
#pragma unroll
                for (int nt = 0; nt < 8; nt++) {
                    const int np = nt >> 1, hf = (nt & 1) * 2;
                    MMA16816(d[mt][nt], ah[mt], bhf[np][hf], bhf[np][hf + 1]);
                    MMA16816(d[mt][nt], ah[mt], blf[np][hf], blf[np][hf + 1]);
                    MMA16816(d[mt][nt], al[mt], bhf[np][hf], bhf[np][hf + 1]);
                }
        }
    }

    // Epilogue: bias (+q scale incl. log2(e)), bf16 hi/lo split, scatter
    const int g = lane >> 2, tig = lane & 3;
    const int which = n0 / C_;
    const int nrel0 = n0 - which * C_;
    const float qscale =
        (which == 0) ? 0.125f * 1.4426950408889634f : 1.0f;
    __nv_bfloat16* mh = (which == 0) ? g_qh : (which == 1) ? g_kh : g_vh;
    __nv_bfloat16* ml = (which == 0) ? g_ql : (which == 1) ? g_kl : g_vl;
#pragma unroll
    for (int mt = 0; mt < 2; mt++) {
        const int m = m0 + wm * 32 + mt * 16 + g;
#pragma unroll
        for (int rr = 0; rr < 2; rr++) {
            const int mr = m + rr * 8;
            const int bb = mr >> 11;
            const int t  = mr & 2047;
#pragma unroll
            for (int nt = 0; nt < 8; nt++) {
                const int nrel = nrel0 + wn * 64 + nt * 8 + 2 * tig;
                const int head = nrel >> 6;
                const int dcol = nrel & 63;
                const float v0 =
                    (d[mt][nt][2 * rr + 0] + bias[which * C_ + nrel]) * qscale;
                const float v1 =
                    (d[mt][nt][2 * rr + 1] + bias[which * C_ + nrel + 1]) * qscale;
                uint32_t lp;
                const uint32_t hp = pack_split(v0, v1, lp);
                const size_t idx = (((size_t)bb * NH_ + head) * T_ + t) * HS_ + dcol;
                *reinterpret_cast<uint32_t*>(mh + idx) = hp;
                *reinterpret_cast<uint32_t*>(ml + idx) = lp;
            }
        }
    }
}

// ---------------------------------------------------------------------------
// Kernel: tensor-core flash attention.
// CTA = (b, h, 64-row q-tile), 128 threads (4 warps x m16). BC=64 keys.
// Q staged through stage-1 K slots (fragments extracted in prologue), so
// smem = 2 KV stages only (72 KB) -> 3 CTAs/SM. Softmax in base-2 domain.
// ---------------------------------------------------------------------------
constexpr int A_LDH   = 72;                          // halves per smem row
constexpr int A_ARR   = 64 * A_LDH * 2;              // 9216 B per 64x64 tile
constexpr int A_KH = 0, A_KL = A_ARR, A_VH = 2 * A_ARR, A_VL = 3 * A_ARR;
constexpr int A_STAGEB = 4 * A_ARR;                  // 36864
constexpr int ATTN_SMEM = 2 * A_STAGEB;              // 73728

__global__ __launch_bounds__(128, 3) void attn_tc(float* __restrict__ out)
{
    extern __shared__ char smc[];
    const uint32_t sb = smem_u32(smc);
    const int tid  = threadIdx.x;
    const int wid  = tid >> 5, lane = tid & 31;
    const int g    = lane >> 2, t = lane & 3;
    const int t4   = lane >> 3, r8 = lane & 7;
    const int qt   = (T_ / 64) - 1 - blockIdx.x;     // heavy tiles first
    const int h    = blockIdx.y;
    const int b    = blockIdx.z;
    const size_t base = ((size_t)b * NH_ + h) * T_ * HS_;

    // ---- async load geometry: thread -> (row = tid/2, 32-half chunk = tid&1)
    const int lrow = tid >> 1;
    const int lcol = (tid & 1) * 32;
    const uint32_t sdst = (uint32_t)((lrow * A_LDH + lcol) * 2);

    auto issue_kv = [&](int j, int s) {
        const uint32_t st = sb + s * A_STAGEB;
        const size_t src = base + (size_t)(j * 64 + lrow) * HS_ + lcol;
#pragma unroll
        for (int i = 0; i < 4; i++) {
            CP_ASYNC16(st + A_KH + sdst + i * 16, g_kh + src + i * 8);
            CP_ASYNC16(st + A_KL + sdst + i * 16, g_kl + src + i * 8);
            CP_ASYNC16(st + A_VH + sdst + i * 16, g_vh + src + i * 8);
            CP_ASYNC16(st + A_VL + sdst + i * 16, g_vl + src + i * 8);
        }
    };

    {   // Q (hi/lo) staged into stage 1's K slots
        const __nv_bfloat16* qh = g_qh + base + (size_t)(qt * 64 + lrow) * HS_ + lcol;
        const __nv_bfloat16* ql = g_ql + base + (size_t)(qt * 64 + lrow) * HS_ + lcol;
        const uint32_t st1 = sb + A_STAGEB;
#pragma unroll
        for (int i = 0; i < 4; i++) {
            CP_ASYNC16(st1 + A_KH + sdst + i * 16, qh + i * 8);
            CP_ASYNC16(st1 + A_KL + sdst + i * 16, ql + i * 8);
        }
    }
    issue_kv(0, 0);
    CP_COMMIT();

    // fragment geometry
    const int a_moff = (t4 & 1) * 8, a_koff = (t4 >> 1) * 8;
    const int b_noff = (t4 >> 1) * 8, b_koff = (t4 & 1) * 8;

    // ---- prologue: wait Q + KV0, extract Q fragments, free stage 1 ----
    uint32_t qhf[4][4], qlf[4][4];
    CP_WAIT0();
    __syncthreads();
#pragma unroll
    for (int ks = 0; ks < 4; ks++) {
        const uint32_t qa = sb + A_STAGEB + A_KH +
            (uint32_t)(((wid * 16 + a_moff + r8) * A_LDH + ks * 16 + a_koff) * 2);
        LDSM4(qhf[ks][0], qhf[ks][1], qhf[ks][2], qhf[ks][3], qa);
        LDSM4(qlf[ks][0], qlf[ks][1], qlf[ks][2], qlf[ks][3], qa + A_ARR);
    }
    __syncthreads();   // all warps have Q fragments; stage 1 reusable

    float o[8][4];
#pragma unroll
    for (int nt = 0; nt < 8; nt++)
#pragma unroll
        for (int e = 0; e < 4; e++) o[nt][e] = 0.0f;
    float m_i[2] = {-INFINITY, -INFINITY};
    float l_i[2] = {0.0f, 0.0f};

    for (int j = 0; j <= qt; j++) {
        if (j < qt) { issue_kv(j + 1, (j + 1) & 1); CP_COMMIT(); }
        if (j < qt) { CP_WAIT1(); } else { CP_WAIT0(); }
        __syncthreads();

        const uint32_t st = sb + (j & 1) * A_STAGEB;

        // ---- S = Q K^T (3-term split) ----
        float s[8][4];
#pragma unroll
        for (int nt = 0; nt < 8; nt++)
#pragma unroll
            for (int e = 0; e < 4; e++) s[nt][e] = 0.0f;

#pragma unroll
        for (int ks = 0; ks < 4; ks++) {
#pragma unroll
            for (int np = 0; np < 4; np++) {
                const uint32_t ka = st + A_KH +
                    (uint32_t)(((np * 16 + b_noff + r8) * A_LDH +
                                ks * 16 + b_koff) * 2);
                uint32_t kh[4], kl[4];
                LDSM4(kh[0], kh[1], kh[2], kh[3], ka);
                LDSM4(kl[0], kl[1], kl[2], kl[3], ka + (A_KL - A_KH));
#pragma unroll
                for (int half = 0; half < 2; half++) {
                    const int nt = np * 2 + half, hf = half * 2;
                    MMA16816(s[nt], qhf[ks], kh[hf], kh[hf + 1]);
                    MMA16816(s[nt], qhf[ks], kl[hf], kl[hf + 1]);
                    MMA16816(s[nt], qlf[ks], kh[hf], kh[hf + 1]);
                }
            }
        }

        // ---- causal mask on diagonal block ----
        if (j == qt) {
            const int r0 = wid * 16 + g;
#pragma unroll
            for (int nt = 0; nt < 8; nt++) {
                const int c0 = nt * 8 + 2 * t;
                if (c0 > r0)          s[nt][0] = -INFINITY;
                if (c0 + 1 > r0)      s[nt][1] = -INFINITY;
                if (c0 > r0 + 8)      s[nt][2] = -INFINITY;
                if (c0 + 1 > r0 + 8)  s[nt][3] = -INFINITY;
            }
        }

        // ---- online softmax (base-2 domain) on fragments ----
        float mx0 = -INFINITY, mx1 = -INFINITY;
#pragma unroll
        for (int nt = 0; nt < 8; nt++) {
            mx0 = fmaxf(mx0, fmaxf(s[nt][0], s[nt][1]));
            mx1 = fmaxf(mx1, fmaxf(s[nt][2], s[nt][3]));
        }
        mx0 = fmaxf(mx0, __shfl_xor_sync(0xffffffffu, mx0, 1));
        mx0 = fmaxf(mx0, __shfl_xor_sync(0xffffffffu, mx0, 2));
        mx1 = fmaxf(mx1, __shfl_xor_sync(0xffffffffu, mx1, 1));
        mx1 = fmaxf(mx1, __shfl_xor_sync(0xffffffffu, mx1, 2));
        const float mn0 = fmaxf(m_i[0], mx0);
        const float mn1 = fmaxf(m_i[1], mx1);
        const float corr0 = ex2(m_i[0] - mn0);
        const float corr1 = ex2(m_i[1] - mn1);
        m_i[0] = mn0; m_i[1] = mn1;

        float sum0 = 0.0f, sum1 = 0.0f;
#pragma unroll
        for (int nt = 0; nt < 8; nt++) {
            s[nt][0] = ex2(s[nt][0] - mn0); sum0 += s[nt][0];
            s[nt][1] = ex2(s[nt][1] - mn0); sum0 += s[nt][1];
            s[nt][2] = ex2(s[nt][2] - mn1); sum1 += s[nt][2];
            s[nt][3] = ex2(s[nt][3] - mn1); sum1 += s[nt][3];
            o[nt][0] *= corr0; o[nt][1] *= corr0;
            o[nt][2] *= corr1; o[nt][3] *= corr1;
        }
        sum0 += __shfl_xor_sync(0xffffffffu, sum0, 1);
        sum0 += __shfl_xor_sync(0xffffffffu, sum0, 2);
        sum1 += __shfl_xor_sync(0xffffffffu, sum1, 1);
        sum1 += __shfl_xor_sync(0xffffffffu, sum1, 2);
        l_i[0] = l_i[0] * corr0 + sum0;
        l_i[1] = l_i[1] * corr1 + sum1;

        // ---- P -> A fragments (bf16 hi/lo split, in registers) ----
        uint32_t ph[4][4], pl[4][4];
#pragma unroll
        for (int ks = 0; ks < 4; ks++) {
            ph[ks][0] = pack_split(s[2 * ks][0],     s[2 * ks][1],     pl[ks][0]);
            ph[ks][1] = pack_split(s[2 * ks][2],     s[2 * ks][3],     pl[ks][1]);
            ph[ks][2] = pack_split(s[2 * ks + 1][0], s[2 * ks + 1][1], pl[ks][2]);
            ph[ks][3] = pack_split(s[2 * ks + 1][2], s[2 * ks + 1][3], pl[ks][3]);
        }

        // ---- O += P V (3-term split), V via ldmatrix.trans ----
#pragma unroll
        for (int ks = 0; ks < 4; ks++) {
#pragma unroll
            for (int dp = 0; dp < 4; dp++) {
                const uint32_t va = st + A_VH +
                    (uint32_t)(((ks * 16 + (t4 & 1) * 8 + r8) * A_LDH +
                                dp * 16 + (t4 >> 1) * 8) * 2);
                uint32_t vh[4], vl[4];
                LDSM4T(vh[0], vh[1], vh[2], vh[3], va);
                LDSM4T(vl[0], vl[1], vl[2], vl[3], va + (A_VL - A_VH));
#pragma unroll
                for (int half = 0; half < 2; half++) {
                    const int nt = dp * 2 + half, hf = half * 2;
                    MMA16816(o[nt], ph[ks], vh[hf], vh[hf + 1]);
                    MMA16816(o[nt], ph[ks], vl[hf], vl[hf + 1]);
                    MMA16816(o[nt], pl[ks], vh[hf], vh[hf + 1]);
                }
            }
        }
        __syncthreads();   // all warps done with this stage before re-fill
    }

    // ---- normalize + write [B, NH, T, HS] ----
    const float inv0 = 1.0f / l_i[0];
    const float inv1 = 1.0f / l_i[1];
    const int r0 = qt * 64 + wid * 16 + g;
#pragma unroll
    for (int nt = 0; nt < 8; nt++) {
        const int col = nt * 8 + 2 * t;
        *reinterpret_cast<float2*>(out + base + (size_t)r0 * HS_ + col) =
            make_float2(o[nt][0] * inv0, o[nt][1] * inv0);
        *reinterpret_cast<float2*>(out + base + (size_t)(r0 + 8) * HS_ + col) =
            make_float2(o[nt][2] * inv1, o[nt][3] * inv1);
    }
}

// ---------------------------------------------------------------------------
extern "C" void kernel_launch(void* const* d_in, const int* in_sizes, int n_in,
                              void* d_out, int out_size)
{
    (void)in_sizes; (void)n_in; (void)out_size;
    const float* x    = (const float*)d_in[0];
    const float* w    = (const float*)d_in[1];
    const float* bias = (const float*)d_in[2];
    float* out = (float*)d_out;

    conv_x_kernel<<<(M_ * K_ / 4 + 255) / 256, 256>>>(x);
    conv_w_kernel<<<((K_ / 4) * N3_ + 255) / 256, 256>>>(w);

    cudaFuncSetAttribute(qkv_gemm_tc,
                         cudaFuncAttributeMaxDynamicSharedMemorySize, GEMM_SMEM);
    dim3 g1(N3_ / 128, M_ / 128);    // (18, 32)
    qkv_gemm_tc<<<g1, 256, GEMM_SMEM>>>(bias);

    cudaFuncSetAttribute(attn_tc,
                         cudaFuncAttributeMaxDynamicSharedMemorySize, ATTN_SMEM);
    dim3 g2(T_ / 64, NH_, B_);       // (32, 12, 2)
    attn_tc<<<g2, 128, ATTN_SMEM>>>(out);
}

// round 12
// speedup vs baseline: 2.3645x; 1.0553x over previous
#include <cuda_runtime.h>
#include <cuda_fp16.h>
#include <math.h>
#include <stdint.h>

// Problem constants
constexpr int B_  = 2;
constexpr int T_  = 2048;
constexpr int C_  = 768;
constexpr int NH_ = 12;
constexpr int HS_ = 64;
constexpr int M_  = B_ * T_;      // 4096
constexpr int N3_ = 3 * C_;       // 2304
constexpr int K_  = C_;           // 768

typedef unsigned long long ull;

// ---------------------------------------------------------------------------
// PTX helpers (base-PTX only: legal at compute_103)
// ---------------------------------------------------------------------------
__device__ __forceinline__ uint32_t smem_u32(const void* p) {
    uint32_t a;
    asm("{ .reg .u64 t; cvta.to.shared.u64 t, %1; cvt.u32.u64 %0, t; }"
        : "=r"(a) : "l"(p));
    return a;
}

#define LDSM4(r0, r1, r2, r3, addr)                                          \
    asm volatile("ldmatrix.sync.aligned.m8n8.x4.shared.b16 {%0,%1,%2,%3}, [%4];" \
                 : "=r"(r0), "=r"(r1), "=r"(r2), "=r"(r3) : "r"(addr))

#define LDSM4T(r0, r1, r2, r3, addr)                                         \
    asm volatile("ldmatrix.sync.aligned.m8n8.x4.trans.shared.b16 {%0,%1,%2,%3}, [%4];" \
                 : "=r"(r0), "=r"(r1), "=r"(r2), "=r"(r3) : "r"(addr))

#define MMA16816(d, a, b0v, b1v)                                             \
    asm volatile("mma.sync.aligned.m16n8k16.row.col.f32.f16.f16.f32 "        \
                 "{%0,%1,%2,%3}, {%4,%5,%6,%7}, {%8,%9}, {%0,%1,%2,%3};"     \
                 : "+f"((d)[0]), "+f"((d)[1]), "+f"((d)[2]), "+f"((d)[3])    \
                 : "r"((a)[0]), "r"((a)[1]), "r"((a)[2]), "r"((a)[3]),       \
                   "r"(b0v), "r"(b1v))

#define CP_ASYNC16(dst, src)                                                 \
    asm volatile("cp.async.cg.shared.global [%0], [%1], 16;"                 \
                 :: "r"(dst), "l"(src) : "memory")
#define CP_COMMIT() asm volatile("cp.async.commit_group;" ::: "memory")
#define CP_WAIT0()  asm volatile("cp.async.wait_group 0;" ::: "memory")
#define CP_WAIT1()  asm volatile("cp.async.wait_group 1;" ::: "memory")

// fast 2^x
__device__ __forceinline__ float ex2(float x) {
    float y; asm("ex2.approx.ftz.f32 %0, %1;" : "=f"(y) : "f"(x)); return y;
}

// pack two f32 into f16x2 (x -> low half, y -> high half)
__device__ __forceinline__ uint32_t pack_h2(float x, float y) {
    uint32_t hp;
    asm("cvt.rn.f16x2.f32 %0, %1, %2;" : "=r"(hp) : "f"(y), "f"(x));
    return hp;
}
// hi/lo split: hi = f16(x),f16(y); lo = residuals
__device__ __forceinline__ uint32_t pack_h2_split(float x, float y, uint32_t& lo) {
    const uint32_t hp = pack_h2(x, y);
    const __half2 hh = *reinterpret_cast<const __half2*>(&hp);
    lo = pack_h2(x - __half2float(hh.x), y - __half2float(hh.y));
    return hp;
}

// ---------------------------------------------------------------------------
// Device scratch (all fp16)
// ---------------------------------------------------------------------------
constexpr size_t QKV_ELEMS = (size_t)B_ * NH_ * T_ * HS_;
__device__ __half g_qh[QKV_ELEMS];   // Q pre-scaled by 0.125*log2(e)
__device__ __half g_ql[QKV_ELEMS];
__device__ __half g_kh[QKV_ELEMS];
__device__ __half g_kl[QKV_ELEMS];
__device__ __half g_vh[QKV_ELEMS];
__device__ __half g_vl[QKV_ELEMS];
__device__ __half g_xh[(size_t)M_ * K_];
__device__ __half g_xl[(size_t)M_ * K_];
__device__ __half g_wth[(size_t)N3_ * K_];   // w transposed [N][K]
__device__ __half g_wtl[(size_t)N3_ * K_];

// ---------------------------------------------------------------------------
// Convert kernels: fp32 -> fp16 hi/lo split (+ transpose for w)
// ---------------------------------------------------------------------------
__global__ __launch_bounds__(256) void conv_x_kernel(const float* __restrict__ x)
{
    const int idx = blockIdx.x * 256 + threadIdx.x;
    if (idx >= M_ * K_ / 4) return;
    float4 v = reinterpret_cast<const float4*>(x)[idx];
    float vv[4] = {v.x, v.y, v.z, v.w};
    ushort hs[4], ls[4];
#pragma unroll
    for (int e = 0; e < 4; e++) {
        __half h = __float2half(vv[e]);
        __half l = __float2half(vv[e] - __half2float(h));
        hs[e] = __half_as_ushort(h);
        ls[e] = __half_as_ushort(l);
    }
    *reinterpret_cast<ushort4*>(&g_xh[(size_t)idx * 4]) =
        make_ushort4(hs[0], hs[1], hs[2], hs[3]);
    *reinterpret_cast<ushort4*>(&g_xl[(size_t)idx * 4]) =
        make_ushort4(ls[0], ls[1], ls[2], ls[3]);
}

__global__ __launch_bounds__(256) void conv_w_kernel(const float* __restrict__ w)
{
    const int idx = blockIdx.x * 256 + threadIdx.x;
    if (idx >= (K_ / 4) * N3_) return;
    const int n  = idx % N3_;
    const int k4 = idx / N3_;
    ushort hs[4], ls[4];
#pragma unroll
    for (int e = 0; e < 4; e++) {
        float v = w[(size_t)(4 * k4 + e) * N3_ + n];
        __half h = __float2half(v);
        __half l = __float2half(v - __half2float(h));
        hs[e] = __half_as_ushort(h);
        ls[e] = __half_as_ushort(l);
    }
    *reinterpret_cast<ushort4*>(&g_wth[(size_t)n * K_ + 4 * k4]) =
        make_ushort4(hs[0], hs[1], hs[2], hs[3]);
    *reinterpret_cast<ushort4*>(&g_wtl[(size_t)n * K_ + 4 * k4]) =
        make_ushort4(ls[0], ls[1], ls[2], ls[3]);
}

// ---------------------------------------------------------------------------
// Kernel: HMMA 3-term split GEMM (fp16), epilogue emits fp16 hi/lo Q(K)(V).
// CTA tile M=128 x N=128, 256 threads (8 warps, warp tile 32x64).
// ---------------------------------------------------------------------------
constexpr int CH  = 32;
constexpr int LDK = 40;
constexpr int NCH = K_ / CH;          // 24
constexpr int ARR_BYTES = 128 * LDK * 2;
constexpr int BUF_BYTES = 4 * ARR_BYTES;
constexpr int OFF_AH = 0;
constexpr int OFF_AL = ARR_BYTES;
constexpr int OFF_BH = 2 * ARR_BYTES;
constexpr int OFF_BL = 3 * ARR_BYTES;
constexpr int GEMM_SMEM = 2 * BUF_BYTES;          // 81920

__global__ __launch_bounds__(256, 1) void qkv_gemm_tc(const float* __restrict__ bias)
{
    extern __shared__ char smem[];
    const uint32_t sb = smem_u32(smem);
    const int tid  = threadIdx.x;
    const int wid  = tid >> 5, lane = tid & 31;
    const int wm   = wid & 3;
    const int wn   = wid >> 2;
    const int m0   = blockIdx.y * 128;
    const int n0   = blockIdx.x * 128;

    const int grow = tid >> 1;
    const int gpart = tid & 1;
    const __half* xh = g_xh + (size_t)(m0 + grow) * K_ + gpart * 16;
    const __half* xl = g_xl + (size_t)(m0 + grow) * K_ + gpart * 16;
    const __half* bh = g_wth + (size_t)(n0 + grow) * K_ + gpart * 16;
    const __half* bl = g_wtl + (size_t)(n0 + grow) * K_ + gpart * 16;
    const uint32_t sdst = sb + (uint32_t)((grow * LDK + gpart * 16) * 2);

    auto issue_loads = [&](int c, int buf) {
        const uint32_t d0 = sdst + buf * BUF_BYTES;
        const int ko = c * CH;
#pragma unroll
        for (int i = 0; i < 2; i++) {
            CP_ASYNC16(d0 + OFF_AH + i * 16, xh + ko + i * 8);
            CP_ASYNC16(d0 + OFF_AL + i * 16, xl + ko + i * 8);
            CP_ASYNC16(d0 + OFF_BH + i * 16, bh + ko + i * 8);
            CP_ASYNC16(d0 + OFF_BL + i * 16, bl + ko + i * 8);
        }
    };

    const int t4 = lane >> 3, r8 = lane & 7;
    const int a_moff = (t4 & 1) * 8, a_koff = (t4 >> 1) * 8;
    const int b_noff = (t4 >> 1) * 8, b_koff = (t4 & 1) * 8;

    float d[2][8][4];
#pragma unroll
    for (int mt = 0; mt < 2; mt++)
#pragma unroll
        for (int nt = 0; nt < 8; nt++)
#pragma unroll
            for (int e = 0; e < 4; e++) d[mt][nt][e] = 0.0f;

    issue_loads(0, 0);
    CP_COMMIT();

    for (int c = 0; c < NCH; c++) {
        CP_WAIT0();
        __syncthreads();
        if (c + 1 < NCH) { issue_loads(c + 1, (c + 1) & 1); }
        CP_COMMIT();

        const uint32_t bufb = sb + (uint32_t)((c & 1) * BUF_BYTES);
#pragma unroll
        for (int ks = 0; ks < 2; ks++) {
            uint32_t ah[2][4], al[2][4];
#pragma unroll
            for (int mt = 0; mt < 2; mt++) {
                const uint32_t ad = bufb + OFF_AH +
                    (uint32_t)(((wm * 32 + mt * 16 + a_moff + r8) * LDK +
                                ks * 16 + a_koff) * 2);
                LDSM4(ah[mt][0], ah[mt][1], ah[mt][2], ah[mt][3], ad);
                LDSM4(al[mt][0], al[mt][1], al[mt][2], al[mt][3],
                      ad + (OFF_AL - OFF_AH));
            }
            uint32_t bhf[4][4], blf[4][4];
#pragma unroll
            for (int np = 0; np < 4; np++) {
                const uint32_t bd = bufb + OFF_BH +
                    (uint32_t)(((wn * 64 + np * 16 + b_noff + r8) * LDK +
                                ks * 16 + b_koff) * 2);
                LDSM4(bhf[np][0], bhf[np][1], bhf[np][2], bhf[np][3], bd);
                LDSM4(blf[np][0], blf[np][1], blf[np][2], blf[np][3],
                      bd + (OFF_BL - OFF_BH));
            }
#pragma unroll
            for (int mt = 0; mt < 2; mt++)
#pragma unroll
                for (int nt = 0; nt < 8; nt++) {
                    const int np = nt >> 1, hf = (nt & 1) * 2;
                    MMA16816(d[mt][nt], ah[mt], bhf[np][hf], bhf[np][hf + 1]);
                    MMA16816(d[mt][nt], ah[mt], blf[np][hf], blf[np][hf + 1]);
                    MMA16816(d[mt][nt], al[mt], bhf[np][hf], bhf[np][hf + 1]);
                }
        }
    }

    // Epilogue: bias (+q scale incl. log2(e)), fp16 hi/lo split, scatter
    const int g = lane >> 2, tig = lane & 3;
    const int which = n0 / C_;
    const int nrel0 = n0 - which * C_;
    const float qscale =
        (which == 0) ? 0.125f * 1.4426950408889634f : 1.0f;
    __half* mh = (which == 0) ? g_qh : (which == 1) ? g_kh : g_vh;
    __half* ml = (which == 0) ? g_ql : (which == 1) ? g_kl : g_vl;
#pragma unroll
    for (int mt = 0; mt < 2; mt++) {
        const int m = m0 + wm * 32 + mt * 16 + g;
#pragma unroll
        for (int rr = 0; rr < 2; rr++) {
            const int mr = m + rr * 8;
            const int bb = mr >> 11;
            const int t  = mr & 2047;
#pragma unroll
            for (int nt = 0; nt < 8; nt++) {
                const int nrel = nrel0 + wn * 64 + nt * 8 + 2 * tig;
                const int head = nrel >> 6;
                const int dcol = nrel & 63;
                const float v0 =
                    (d[mt][nt][2 * rr + 0] + bias[which * C_ + nrel]) * qscale;
                const float v1 =
                    (d[mt][nt][2 * rr + 1] + bias[which * C_ + nrel + 1]) * qscale;
                uint32_t lp;
                const uint32_t hp = pack_h2_split(v0, v1, lp);
                const size_t idx = (((size_t)bb * NH_ + head) * T_ + t) * HS_ + dcol;
                *reinterpret_cast<uint32_t*>(mh + idx) = hp;
                *reinterpret_cast<uint32_t*>(ml + idx) = lp;
            }
        }
    }
}

// ---------------------------------------------------------------------------
// Kernel: tensor-core flash attention (fp16).
// CTA = (b, h, 64-row q-tile), 128 threads (4 warps x m16). BC=64 keys.
// S = QK^T 3-term fp16 split; softmax base-2; P single fp16 (2^-11 rel err);
// O += P V 2-term (V hi/lo). Q staged through stage-1 K slots; 2 KV stages.
// ---------------------------------------------------------------------------
constexpr int A_LDH   = 72;                          // halves per smem row
constexpr int A_ARR   = 64 * A_LDH * 2;              // 9216 B per 64x64 tile
constexpr int A_KH = 0, A_KL = A_ARR, A_VH = 2 * A_ARR, A_VL = 3 * A_ARR;
constexpr int A_STAGEB = 4 * A_ARR;                  // 36864
constexpr int ATTN_SMEM = 2 * A_STAGEB;              // 73728

__global__ __launch_bounds__(128, 3) void attn_tc(float* __restrict__ out)
{
    extern __shared__ char smc[];
    const uint32_t sb = smem_u32(smc);
    const int tid  = threadIdx.x;
    const int wid  = tid >> 5, lane = tid & 31;
    const int g    = lane >> 2, t = lane & 3;
    const int t4   = lane >> 3, r8 = lane & 7;
    const int qt   = (T_ / 64) - 1 - blockIdx.x;     // heavy tiles first
    const int h    = blockIdx.y;
    const int b    = blockIdx.z;
    const size_t base = ((size_t)b * NH_ + h) * T_ * HS_;

    // ---- async load geometry: thread -> (row = tid/2, 32-half chunk = tid&1)
    const int lrow = tid >> 1;
    const int lcol = (tid & 1) * 32;
    const uint32_t sdst = (uint32_t)((lrow * A_LDH + lcol) * 2);

    auto issue_kv = [&](int j, int s) {
        const uint32_t st = sb + s * A_STAGEB;
        const size_t src = base + (size_t)(j * 64 + lrow) * HS_ + lcol;
#pragma unroll
        for (int i = 0; i < 4; i++) {
            CP_ASYNC16(st + A_KH + sdst + i * 16, g_kh + src + i * 8);
            CP_ASYNC16(st + A_KL + sdst + i * 16, g_kl + src + i * 8);
            CP_ASYNC16(st + A_VH + sdst + i * 16, g_vh + src + i * 8);
            CP_ASYNC16(st + A_VL + sdst + i * 16, g_vl + src + i * 8);
        }
    };

    {   // Q (hi/lo) staged into stage 1's K slots
        const __half* qh = g_qh + base + (size_t)(qt * 64 + lrow) * HS_ + lcol;
        const __half* ql = g_ql + base + (size_t)(qt * 64 + lrow) * HS_ + lcol;
        const uint32_t st1 = sb + A_STAGEB;
#pragma unroll
        for (int i = 0; i < 4; i++) {
            CP_ASYNC16(st1 + A_KH + sdst + i * 16, qh + i * 8);
            CP_ASYNC16(st1 + A_KL + sdst + i * 16, ql + i * 8);
        }
    }
    issue_kv(0, 0);
    CP_COMMIT();

    // fragment geometry
    const int a_moff = (t4 & 1) * 8, a_koff = (t4 >> 1) * 8;
    const int b_noff = (t4 >> 1) * 8, b_koff = (t4 & 1) * 8;

    // ---- prologue: wait Q + KV0, extract Q fragments, free stage 1 ----
    uint32_t qhf[4][4], qlf[4][4];
    CP_WAIT0();
    __syncthreads();
#pragma unroll
    for (int ks = 0; ks < 4; ks++) {
        const uint32_t qa = sb + A_STAGEB + A_KH +
            (uint32_t)(((wid * 16 + a_moff + r8) * A_LDH + ks * 16 + a_koff) * 2);
        LDSM4(qhf[ks][0], qhf[ks][1], qhf[ks][2], qhf[ks][3], qa);
        LDSM4(qlf[ks][0], qlf[ks][1], qlf[ks][2], qlf[ks][3], qa + A_ARR);
    }
    __syncthreads();   // all warps have Q fragments; stage 1 reusable

    float o[8][4];
#pragma unroll
    for (int nt = 0; nt < 8; nt++)
#pragma unroll
        for (int e = 0; e < 4; e++) o[nt][e] = 0.0f;
    float m_i[2] = {-INFINITY, -INFINITY};
    float l_i[2] = {0.0f, 0.0f};

    for (int j = 0; j <= qt; j++) {
        if (j < qt) { issue_kv(j + 1, (j + 1) & 1); CP_COMMIT(); }
        if (j < qt) { CP_WAIT1(); } else { CP_WAIT0(); }
        __syncthreads();

        const uint32_t st = sb + (j & 1) * A_STAGEB;

        // ---- S = Q K^T (3-term fp16 split) ----
        float s[8][4];
#pragma unroll
        for (int nt = 0; nt < 8; nt++)
#pragma unroll
            for (int e = 0; e < 4; e++) s[nt][e] = 0.0f;

#pragma unroll
        for (int ks = 0; ks < 4; ks++) {
#pragma unroll
            for (int np = 0; np < 4; np++) {
                const uint32_t ka = st + A_KH +
                    (uint32_t)(((np * 16 + b_noff + r8) * A_LDH +
                                ks * 16 + b_koff) * 2);
                uint32_t kh[4], kl[4];
                LDSM4(kh[0], kh[1], kh[2], kh[3], ka);
                LDSM4(kl[0], kl[1], kl[2], kl[3], ka + (A_KL - A_KH));
#pragma unroll
                for (int half = 0; half < 2; half++) {
                    const int nt = np * 2 + half, hf = half * 2;
                    MMA16816(s[nt], qhf[ks], kh[hf], kh[hf + 1]);
                    MMA16816(s[nt], qhf[ks], kl[hf], kl[hf + 1]);
                    MMA16816(s[nt], qlf[ks], kh[hf], kh[hf + 1]);
                }
            }
        }

        // ---- causal mask on diagonal block ----
        if (j == qt) {
            const int r0 = wid * 16 + g;
#pragma unroll
            for (int nt = 0; nt < 8; nt++) {
                const int c0 = nt * 8 + 2 * t;
                if (c0 > r0)          s[nt][0] = -INFINITY;
                if (c0 + 1 > r0)      s[nt][1] = -INFINITY;
                if (c0 > r0 + 8)      s[nt][2] = -INFINITY;
                if (c0 + 1 > r0 + 8)  s[nt][3] = -INFINITY;
            }
        }

        // ---- online softmax (base-2 domain) on fragments ----
        float mx0 = -INFINITY, mx1 = -INFINITY;
#pragma unroll
        for (int nt = 0; nt < 8; nt++) {
            mx0 = fmaxf(mx0, fmaxf(s[nt][0], s[nt][1]));
            mx1 = fmaxf(mx1, fmaxf(s[nt][2], s[nt][3]));
        }
        mx0 = fmaxf(mx0, __shfl_xor_sync(0xffffffffu, mx0, 1));
        mx0 = fmaxf(mx0, __shfl_xor_sync(0xffffffffu, mx0, 2));
        mx1 = fmaxf(mx1, __shfl_xor_sync(0xffffffffu, mx1, 1));
        mx1 = fmaxf(mx1, __shfl_xor_sync(0xffffffffu, mx1, 2));
        const float mn0 = fmaxf(m_i[0], mx0);
        const float mn1 = fmaxf(m_i[1], mx1);
        const float corr0 = ex2(m_i[0] - mn0);
        const float corr1 = ex2(m_i[1] - mn1);
        m_i[0] = mn0; m_i[1] = mn1;

        float sum0 = 0.0f, sum1 = 0.0f;
#pragma unroll
        for (int nt = 0; nt < 8; nt++) {
            s[nt][0] = ex2(s[nt][0] - mn0); sum0 += s[nt][0];
            s[nt][1] = ex2(s[nt][1] - mn0); sum0 += s[nt][1];
            s[nt][2] = ex2(s[nt][2] - mn1); sum1 += s[nt][2];
            s[nt][3] = ex2(s[nt][3] - mn1); sum1 += s[nt][3];
            o[nt][0] *= corr0; o[nt][1] *= corr0;
            o[nt][2] *= corr1; o[nt][3] *= corr1;
        }
        sum0 += __shfl_xor_sync(0xffffffffu, sum0, 1);
        sum0 += __shfl_xor_sync(0xffffffffu, sum0, 2);
        sum1 += __shfl_xor_sync(0xffffffffu, sum1, 1);
        sum1 += __shfl_xor_sync(0xffffffffu, sum1, 2);
        l_i[0] = l_i[0] * corr0 + sum0;
        l_i[1] = l_i[1] * corr1 + sum1;

        // ---- P -> A fragments (single fp16; 2^-11 rel err OK) ----
        uint32_t ph[4][4];
#pragma unroll
        for (int ks = 0; ks < 4; ks++) {
            ph[ks][0] = pack_h2(s[2 * ks][0],     s[2 * ks][1]);
            ph[ks][1] = pack_h2(s[2 * ks][2],     s[2 * ks][3]);
            ph[ks][2] = pack_h2(s[2 * ks + 1][0], s[2 * ks + 1][1]);
            ph[ks][3] = pack_h2(s[2 * ks + 1][2], s[2 * ks + 1][3]);
        }

        // ---- O += P V (2-term: V hi/lo), V via ldmatrix.trans ----
#pragma unroll
        for (int ks = 0; ks < 4; ks++) {
#pragma unroll
            for (int dp = 0; dp < 4; dp++) {
                const uint32_t va = st + A_VH +
                    (uint32_t)(((ks * 16 + (t4 & 1) * 8 + r8) * A_LDH +
                                dp * 16 + (t4 >> 1) * 8) * 2);
                uint32_t vh[4], vl[4];
                LDSM4T(vh[0], vh[1], vh[2], vh[3], va);
                LDSM4T(vl[0], vl[1], vl[2], vl[3], va + (A_VL - A_VH));
#pragma unroll
                for (int half = 0; half < 2; half++) {
                    const int nt = dp * 2 + half, hf = half * 2;
                    MMA16816(o[nt], ph[ks], vh[hf], vh[hf + 1]);
                    MMA16816(o[nt], ph[ks], vl[hf], vl[hf + 1]);
                }
            }
        }
        __syncthreads();   // all warps done with this stage before re-fill
    }

    // ---- normalize + write [B, NH, T, HS] ----
    const float inv0 = 1.0f / l_i[0];
    const float inv1 = 1.0f / l_i[1];
    const int r0 = qt * 64 + wid * 16 + g;
#pragma unroll
    for (int nt = 0; nt < 8; nt++) {
        const int col = nt * 8 + 2 * t;
        *reinterpret_cast<float2*>(out + base + (size_t)r0 * HS_ + col) =
            make_float2(o[nt][0] * inv0, o[nt][1] * inv0);
        *reinterpret_cast<float2*>(out + base + (size_t)(r0 + 8) * HS_ + col) =
            make_float2(o[nt][2] * inv1, o[nt][3] * inv1);
    }
}

// ---------------------------------------------------------------------------
extern "C" void kernel_launch(void* const* d_in, const int* in_sizes, int n_in,
                              void* d_out, int out_size)
{
    (void)in_sizes; (void)n_in; (void)out_size;
    const float* x    = (const float*)d_in[0];
    const float* w    = (const float*)d_in[1];
    const float* bias = (const float*)d_in[2];
    float* out = (float*)d_out;

    conv_x_kernel<<<(M_ * K_ / 4 + 255) / 256, 256>>>(x);
    conv_w_kernel<<<((K_ / 4) * N3_ + 255) / 256, 256>>>(w);

    cudaFuncSetAttribute(qkv_gemm_tc,
                         cudaFuncAttributeMaxDynamicSharedMemorySize, GEMM_SMEM);
    dim3 g1(N3_ / 128, M_ / 128);    // (18, 32)
    qkv_gemm_tc<<<g1, 256, GEMM_SMEM>>>(bias);

    cudaFuncSetAttribute(attn_tc,
                         cudaFuncAttributeMaxDynamicSharedMemorySize, ATTN_SMEM);
    dim3 g2(T_ / 64, NH_, B_);       // (32, 12, 2)
    attn_tc<<<g2, 128, ATTN_SMEM>>>(out);
}

// round 14
// speedup vs baseline: 2.7244x; 1.1522x over previous
#include <cuda_runtime.h>
#include <cuda_fp16.h>
#include <math.h>
#include <stdint.h>

// Problem constants
constexpr int B_  = 2;
constexpr int T_  = 2048;
constexpr int C_  = 768;
constexpr int NH_ = 12;
constexpr int HS_ = 64;
constexpr int M_  = B_ * T_;      // 4096
constexpr int N3_ = 3 * C_;       // 2304
constexpr int K_  = C_;           // 768

typedef unsigned long long ull;

// ---------------------------------------------------------------------------
// PTX helpers (base-PTX only: legal at compute_103)
// ---------------------------------------------------------------------------
__device__ __forceinline__ uint32_t smem_u32(const void* p) {
    uint32_t a;
    asm("{ .reg .u64 t; cvta.to.shared.u64 t, %1; cvt.u32.u64 %0, t; }"
        : "=r"(a) : "l"(p));
    return a;
}

#define LDSM4(r0, r1, r2, r3, addr)                                          \
    asm volatile("ldmatrix.sync.aligned.m8n8.x4.shared.b16 {%0,%1,%2,%3}, [%4];" \
                 : "=r"(r0), "=r"(r1), "=r"(r2), "=r"(r3) : "r"(addr))

#define LDSM4T(r0, r1, r2, r3, addr)                                         \
    asm volatile("ldmatrix.sync.aligned.m8n8.x4.trans.shared.b16 {%0,%1,%2,%3}, [%4];" \
                 : "=r"(r0), "=r"(r1), "=r"(r2), "=r"(r3) : "r"(addr))

#define MMA16816(d, a, b0v, b1v)                                             \
    asm volatile("mma.sync.aligned.m16n8k16.row.col.f32.f16.f16.f32 "        \
                 "{%0,%1,%2,%3}, {%4,%5,%6,%7}, {%8,%9}, {%0,%1,%2,%3};"     \
                 : "+f"((d)[0]), "+f"((d)[1]), "+f"((d)[2]), "+f"((d)[3])    \
                 : "r"((a)[0]), "r"((a)[1]), "r"((a)[2]), "r"((a)[3]),       \
                   "r"(b0v), "r"(b1v))

#define CP_ASYNC16(dst, src)                                                 \
    asm volatile("cp.async.cg.shared.global [%0], [%1], 16;"                 \
                 :: "r"(dst), "l"(src) : "memory")
#define CP_COMMIT() asm volatile("cp.async.commit_group;" ::: "memory")
#define CP_WAIT0()  asm volatile("cp.async.wait_group 0;" ::: "memory")
#define CP_WAIT1()  asm volatile("cp.async.wait_group 1;" ::: "memory")

// fast 2^x
__device__ __forceinline__ float ex2(float x) {
    float y; asm("ex2.approx.ftz.f32 %0, %1;" : "=f"(y) : "f"(x)); return y;
}

// pack two f32 into f16x2 (x -> low half, y -> high half)
__device__ __forceinline__ uint32_t pack_h2(float x, float y) {
    uint32_t hp;
    asm("cvt.rn.f16x2.f32 %0, %1, %2;" : "=r"(hp) : "f"(y), "f"(x));
    return hp;
}
// hi/lo split: hi = f16(x),f16(y); lo = residuals
__device__ __forceinline__ uint32_t pack_h2_split(float x, float y, uint32_t& lo) {
    const uint32_t hp = pack_h2(x, y);
    const __half2 hh = *reinterpret_cast<const __half2*>(&hp);
    lo = pack_h2(x - __half2float(hh.x), y - __half2float(hh.y));
    return hp;
}

// ---------------------------------------------------------------------------
// Device scratch (all fp16)
// ---------------------------------------------------------------------------
constexpr size_t QKV_ELEMS = (size_t)B_ * NH_ * T_ * HS_;
__device__ __half g_qh[QKV_ELEMS];   // Q pre-scaled by 0.125*log2(e)
__device__ __half g_ql[QKV_ELEMS];
__device__ __half g_kh[QKV_ELEMS];
__device__ __half g_kl[QKV_ELEMS];
__device__ __half g_vh[QKV_ELEMS];   // V single fp16 (no residual)
__device__ __half g_xh[(size_t)M_ * K_];
__device__ __half g_xl[(size_t)M_ * K_];
__device__ __half g_wth[(size_t)N3_ * K_];   // w transposed [N][K]
__device__ __half g_wtl[(size_t)N3_ * K_];

// ---------------------------------------------------------------------------
// Convert kernels: fp32 -> fp16 hi/lo split (+ transpose for w)
// ---------------------------------------------------------------------------
__global__ __launch_bounds__(256) void conv_x_kernel(const float* __restrict__ x)
{
    const int idx = blockIdx.x * 256 + threadIdx.x;
    if (idx >= M_ * K_ / 4) return;
    float4 v = reinterpret_cast<const float4*>(x)[idx];
    float vv[4] = {v.x, v.y, v.z, v.w};
    ushort hs[4], ls[4];
#pragma unroll
    for (int e = 0; e < 4; e++) {
        __half h = __float2half(vv[e]);
        __half l = __float2half(vv[e] - __half2float(h));
        hs[e] = __half_as_ushort(h);
        ls[e] = __half_as_ushort(l);
    }
    *reinterpret_cast<ushort4*>(&g_xh[(size_t)idx * 4]) =
        make_ushort4(hs[0], hs[1], hs[2], hs[3]);
    *reinterpret_cast<ushort4*>(&g_xl[(size_t)idx * 4]) =
        make_ushort4(ls[0], ls[1], ls[2], ls[3]);
}

__global__ __launch_bounds__(256) void conv_w_kernel(const float* __restrict__ w)
{
    const int idx = blockIdx.x * 256 + threadIdx.x;
    if (idx >= (K_ / 4) * N3_) return;
    const int n  = idx % N3_;
    const int k4 = idx / N3_;
    ushort hs[4], ls[4];
#pragma unroll
    for (int e = 0; e < 4; e++) {
        float v = w[(size_t)(4 * k4 + e) * N3_ + n];
        __half h = __float2half(v);
        __half l = __float2half(v - __half2float(h));
        hs[e] = __half_as_ushort(h);
        ls[e] = __half_as_ushort(l);
    }
    *reinterpret_cast<ushort4*>(&g_wth[(size_t)n * K_ + 4 * k4]) =
        make_ushort4(hs[0], hs[1], hs[2], hs[3]);
    *reinterpret_cast<ushort4*>(&g_wtl[(size_t)n * K_ + 4 * k4]) =
        make_ushort4(ls[0], ls[1], ls[2], ls[3]);
}

// ---------------------------------------------------------------------------
// Kernel: HMMA 3-term split GEMM (fp16), epilogue emits fp16 Q/K (hi/lo), V (hi).
// CTA tile M=128 x N=128, 256 threads (8 warps, warp tile 32x64), 2 CTAs/SM.
// ---------------------------------------------------------------------------
constexpr int CH  = 32;
constexpr int LDK = 40;
constexpr int NCH = K_ / CH;          // 24
constexpr int ARR_BYTES = 128 * LDK * 2;
constexpr int BUF_BYTES = 4 * ARR_BYTES;
constexpr int OFF_AH = 0;
constexpr int OFF_AL = ARR_BYTES;
constexpr int OFF_BH = 2 * ARR_BYTES;
constexpr int OFF_BL = 3 * ARR_BYTES;
constexpr int GEMM_SMEM = 2 * BUF_BYTES;          // 81920

__global__ __launch_bounds__(256, 2) void qkv_gemm_tc(const float* __restrict__ bias)
{
    extern __shared__ char smem[];
    const uint32_t sb = smem_u32(smem);
    const int tid  = threadIdx.x;
    const int wid  = tid >> 5, lane = tid & 31;
    const int wm   = wid & 3;
    const int wn   = wid >> 2;
    const int m0   = blockIdx.y * 128;
    const int n0   = blockIdx.x * 128;

    const int grow = tid >> 1;
    const int gpart = tid & 1;
    const __half* xh = g_xh + (size_t)(m0 + grow) * K_ + gpart * 16;
    const __half* xl = g_xl + (size_t)(m0 + grow) * K_ + gpart * 16;
    const __half* bh = g_wth + (size_t)(n0 + grow) * K_ + gpart * 16;
    const __half* bl = g_wtl + (size_t)(n0 + grow) * K_ + gpart * 16;
    const uint32_t sdst = sb + (uint32_t)((grow * LDK + gpart * 16) * 2);

    auto issue_loads = [&](int c, int buf) {
        const uint32_t d0 = sdst + buf * BUF_BYTES;
        const int ko = c * CH;
#pragma unroll
        for (int i = 0; i < 2; i++) {
            CP_ASYNC16(d0 + OFF_AH + i * 16, xh + ko + i * 8);
            CP_ASYNC16(d0 + OFF_AL + i * 16, xl + ko + i * 8);
            CP_ASYNC16(d0 + OFF_BH + i * 16, bh + ko + i * 8);
            CP_ASYNC16(d0 + OFF_BL + i * 16, bl + ko + i * 8);
        }
    };

    const int t4 = lane >> 3, r8 = lane & 7;
    const int a_moff = (t4 & 1) * 8, a_koff = (t4 >> 1) * 8;
    const int b_noff = (t4 >> 1) * 8, b_koff = (t4 & 1) * 8;

    float d[2][8][4];
#pragma unroll
    for (int mt = 0; mt < 2; mt++)
#pragma unroll
        for (int nt = 0; nt < 8; nt++)
#pragma unroll
            for (int e = 0; e < 4; e++) d[mt][nt][e] = 0.0f;

    issue_loads(0, 0);
    CP_COMMIT();

    for (int c = 0; c < NCH; c++) {
        CP_WAIT0();
        __syncthreads();
        if (c + 1 < NCH) { issue_loads(c + 1, (c + 1) & 1); }
        CP_COMMIT();

        const uint32_t bufb = sb + (uint32_t)((c & 1) * BUF_BYTES);
#pragma unroll
        for (int ks = 0; ks < 2; ks++) {
            uint32_t ah[2][4], al[2][4];
#pragma unroll
            for (int mt = 0; mt < 2; mt++) {
                const uint32_t ad = bufb + OFF_AH +
                    (uint32_t)(((wm * 32 + mt * 16 + a_moff + r8) * LDK +
                                ks * 16 + a_koff) * 2);
                LDSM4(ah[mt][0], ah[mt][1], ah[mt][2], ah[mt][3], ad);
                LDSM4(al[mt][0], al[mt][1], al[mt][2], al[mt][3],
                      ad + (OFF_AL - OFF_AH));
            }
            // per-np B-fragment loads (keeps live b-regs at 8 -> 2 CTAs/SM)
#pragma unroll
            for (int np = 0; np < 4; np++) {
                const uint32_t bd = bufb + OFF_BH +
                    (uint32_t)(((wn * 64 + np * 16 + b_noff + r8) * LDK +
                                ks * 16 + b_koff) * 2);
                uint32_t bhf[4], blf[4];
                LDSM4(bhf[0], bhf[1], bhf[2], bhf[3], bd);
                LDSM4(blf[0], blf[1], blf[2], blf[3], bd + (OFF_BL - OFF_BH));
#pragma unroll
                for (int mt = 0; mt < 2; mt++)
#pragma unroll
                    for (int half = 0; half < 2; half++) {
                        const int nt = np * 2 + half, hf = half * 2;
                        MMA16816(d[mt][nt], ah[mt], bhf[hf], bhf[hf + 1]);
                        MMA16816(d[mt][nt], ah[mt], blf[hf], blf[hf + 1]);
                        MMA16816(d[mt][nt], al[mt], bhf[hf], bhf[hf + 1]);
                    }
            }
        }
    }

    // Epilogue: bias (+q scale incl. log2(e)), fp16 split, scatter
    const int g = lane >> 2, tig = lane & 3;
    const int which = n0 / C_;
    const int nrel0 = n0 - which * C_;
    const float qscale =
        (which == 0) ? 0.125f * 1.4426950408889634f : 1.0f;
    __half* mh = (which == 0) ? g_qh : (which == 1) ? g_kh : g_vh;
    __half* ml = (which == 0) ? g_ql : (which == 1) ? g_kl : nullptr;
#pragma unroll
    for (int mt = 0; mt < 2; mt++) {
        const int m = m0 + wm * 32 + mt * 16 + g;
#pragma unroll
        for (int rr = 0; rr < 2; rr++) {
            const int mr = m + rr * 8;
            const int bb = mr >> 11;
            const int t  = mr & 2047;
#pragma unroll
            for (int nt = 0; nt < 8; nt++) {
                const int nrel = nrel0 + wn * 64 + nt * 8 + 2 * tig;
                const int head = nrel >> 6;
                const int dcol = nrel & 63;
                const float v0 =
                    (d[mt][nt][2 * rr + 0] + bias[which * C_ + nrel]) * qscale;
                const float v1 =
                    (d[mt][nt][2 * rr + 1] + bias[which * C_ + nrel + 1]) * qscale;
                const size_t idx = (((size_t)bb * NH_ + head) * T_ + t) * HS_ + dcol;
                if (which == 2) {
                    *reinterpret_cast<uint32_t*>(mh + idx) = pack_h2(v0, v1);
                } else {
                    uint32_t lp;
                    const uint32_t hp = pack_h2_split(v0, v1, lp);
                    *reinterpret_cast<uint32_t*>(mh + idx) = hp;
                    *reinterpret_cast<uint32_t*>(ml + idx) = lp;
                }
            }
        }
    }
}

// ---------------------------------------------------------------------------
// Kernel: tensor-core flash attention (fp16).
// CTA = (b, h, 64-row q-tile), 128 threads (4 warps x m16). BC=64 keys.
// S = QK^T 3-term fp16 split; softmax base-2; P single fp16; V single fp16
// (1-term PV). Q staged through stage-1 K slots; 2 KV stages (55 KB).
// ---------------------------------------------------------------------------
constexpr int A_LDH   = 72;                          // halves per smem row
constexpr int A_ARR   = 64 * A_LDH * 2;              // 9216 B per 64x64 tile
constexpr int A_KH = 0, A_KL = A_ARR, A_VH = 2 * A_ARR;
constexpr int A_STAGEB = 3 * A_ARR;                  // 27648
constexpr int ATTN_SMEM = 2 * A_STAGEB;              // 55296

__global__ __launch_bounds__(128, 3) void attn_tc(float* __restrict__ out)
{
    extern __shared__ char smc[];
    const uint32_t sb = smem_u32(smc);
    const int tid  = threadIdx.x;
    const int wid  = tid >> 5, lane = tid & 31;
    const int g    = lane >> 2, t = lane & 3;
    const int t4   = lane >> 3, r8 = lane & 7;
    const int qt   = (T_ / 64) - 1 - blockIdx.x;     // heavy tiles first
    const int h    = blockIdx.y;
    const int b    = blockIdx.z;
    const size_t base = ((size_t)b * NH_ + h) * T_ * HS_;

    // ---- async load geometry: thread -> (row = tid/2, 32-half chunk = tid&1)
    const int lrow = tid >> 1;
    const int lcol = (tid & 1) * 32;
    const uint32_t sdst = (uint32_t)((lrow * A_LDH + lcol) * 2);

    auto issue_kv = [&](int j, int s) {
        const uint32_t st = sb + s * A_STAGEB;
        const size_t src = base + (size_t)(j * 64 + lrow) * HS_ + lcol;
#pragma unroll
        for (int i = 0; i < 4; i++) {
            CP_ASYNC16(st + A_KH + sdst + i * 16, g_kh + src + i * 8);
            CP_ASYNC16(st + A_KL + sdst + i * 16, g_kl + src + i * 8);
            CP_ASYNC16(st + A_VH + sdst + i * 16, g_vh + src + i * 8);
        }
    };

    {   // Q (hi/lo) staged into stage 1's K slots
        const __half* qh = g_qh + base + (size_t)(qt * 64 + lrow) * HS_ + lcol;
        const __half* ql = g_ql + base + (size_t)(qt * 64 + lrow) * HS_ + lcol;
        const uint32_t st1 = sb + A_STAGEB;
#pragma unroll
        for (int i = 0; i < 4; i++) {
            CP_ASYNC16(st1 + A_KH + sdst + i * 16, qh + i * 8);
            CP_ASYNC16(st1 + A_KL + sdst + i * 16, ql + i * 8);
        }
    }
    issue_kv(0, 0);
    CP_COMMIT();

    // fragment geometry
    const int a_moff = (t4 & 1) * 8, a_koff = (t4 >> 1) * 8;
    const int b_noff = (t4 >> 1) * 8, b_koff = (t4 & 1) * 8;

    // ---- prologue: wait Q + KV0, extract Q fragments, free stage 1 ----
    uint32_t qhf[4][4], qlf[4][4];
    CP_WAIT0();
    __syncthreads();
#pragma unroll
    for (int ks = 0; ks < 4; ks++) {
        const uint32_t qa = sb + A_STAGEB + A_KH +
            (uint32_t)(((wid * 16 + a_moff + r8) * A_LDH + ks * 16 + a_koff) * 2);
        LDSM4(qhf[ks][0], qhf[ks][1], qhf[ks][2], qhf[ks][3], qa);
        LDSM4(qlf[ks][0], qlf[ks][1], qlf[ks][2], qlf[ks][3], qa + A_ARR);
    }
    __syncthreads();   // all warps have Q fragments; stage 1 reusable

    float o[8][4];
#pragma unroll
    for (int nt = 0; nt < 8; nt++)
#pragma unroll
        for (int e = 0; e < 4; e++) o[nt][e] = 0.0f;
    float m_i[2] = {-INFINITY, -INFINITY};
    float l_i[2] = {0.0f, 0.0f};

    for (int j = 0; j <= qt; j++) {
        if (j < qt) { issue_kv(j + 1, (j + 1) & 1); CP_COMMIT(); }
        if (j < qt) { CP_WAIT1(); } else { CP_WAIT0(); }
        __syncthreads();

        const uint32_t st = sb + (j & 1) * A_STAGEB;

        // ---- S = Q K^T (3-term fp16 split) ----
        float s[8][4];
#pragma unroll
        for (int nt = 0; nt < 8; nt++)
#pragma unroll
            for (int e = 0; e < 4; e++) s[nt][e] = 0.0f;

#pragma unroll
        for (int ks = 0; ks < 4; ks++) {
#pragma unroll
            for (int np = 0; np < 4; np++) {
                const uint32_t ka = st + A_KH +
                    (uint32_t)(((np * 16 + b_noff + r8) * A_LDH +
                                ks * 16 + b_koff) * 2);
                uint32_t kh[4], kl[4];
                LDSM4(kh[0], kh[1], kh[2], kh[3], ka);
                LDSM4(kl[0], kl[1], kl[2], kl[3], ka + (A_KL - A_KH));
#pragma unroll
                for (int half = 0; half < 2; half++) {
                    const int nt = np * 2 + half, hf = half * 2;
                    MMA16816(s[nt], qhf[ks], kh[hf], kh[hf + 1]);
                    MMA16816(s[nt], qhf[ks], kl[hf], kl[hf + 1]);
                    MMA16816(s[nt], qlf[ks], kh[hf], kh[hf + 1]);
                }
            }
        }

        // ---- causal mask on diagonal block ----
        if (j == qt) {
            const int r0 = wid * 16 + g;
#pragma unroll
            for (int nt = 0; nt < 8; nt++) {
                const int c0 = nt * 8 + 2 * t;
                if (c0 > r0)          s[nt][0] = -INFINITY;
                if (c0 + 1 > r0)      s[nt][1] = -INFINITY;
                if (c0 > r0 + 8)      s[nt][2] = -INFINITY;
                if (c0 + 1 > r0 + 8)  s[nt][3] = -INFINITY;
            }
        }

        // ---- online softmax (base-2 domain) on fragments ----
        float mx0 = -INFINITY, mx1 = -INFINITY;
#pragma unroll
        for (int nt = 0; nt < 8; nt++) {
            mx0 = fmaxf(mx0, fmaxf(s[nt][0], s[nt][1]));
            mx1 = fmaxf(mx1, fmaxf(s[nt][2], s[nt][3]));
        }
        mx0 = fmaxf(mx0, __shfl_xor_sync(0xffffffffu, mx0, 1));
        mx0 = fmaxf(mx0, __shfl_xor_sync(0xffffffffu, mx0, 2));
        mx1 = fmaxf(mx1, __shfl_xor_sync(0xffffffffu, mx1, 1));
        mx1 = fmaxf(mx1, __shfl_xor_sync(0xffffffffu, mx1, 2));
        const float mn0 = fmaxf(m_i[0], mx0);
        const float mn1 = fmaxf(m_i[1], mx1);
        const float corr0 = ex2(m_i[0] - mn0);
        const float corr1 = ex2(m_i[1] - mn1);
        m_i[0] = mn0; m_i[1] = mn1;

        float sum0 = 0.0f, sum1 = 0.0f;
#pragma unroll
        for (int nt = 0; nt < 8; nt++) {
            s[nt][0] = ex2(s[nt][0] - mn0); sum0 += s[nt][0];
            s[nt][1] = ex2(s[nt][1] - mn0); sum0 += s[nt][1];
            s[nt][2] = ex2(s[nt][2] - mn1); sum1 += s[nt][2];
            s[nt][3] = ex2(s[nt][3] - mn1); sum1 += s[nt][3];
            o[nt][0] *= corr0; o[nt][1] *= corr0;
            o[nt][2] *= corr1; o[nt][3] *= corr1;
        }
        sum0 += __shfl_xor_sync(0xffffffffu, sum0, 1);
        sum0 += __shfl_xor_sync(0xffffffffu, sum0, 2);
        sum1 += __shfl_xor_sync(0xffffffffu, sum1, 1);
        sum1 += __shfl_xor_sync(0xffffffffu, sum1, 2);
        l_i[0] = l_i[0] * corr0 + sum0;
        l_i[1] = l_i[1] * corr1 + sum1;

        // ---- P -> A fragments (single fp16) ----
        uint32_t ph[4][4];
#pragma unroll
        for (int ks = 0; ks < 4; ks++) {
            ph[ks][0] = pack_h2(s[2 * ks][0],     s[2 * ks][1]);
            ph[ks][1] = pack_h2(s[2 * ks][2],     s[2 * ks][3]);
            ph[ks][2] = pack_h2(s[2 * ks + 1][0], s[2 * ks + 1][1]);
            ph[ks][3] = pack_h2(s[2 * ks + 1][2], s[2 * ks + 1][3]);
        }

        // ---- O += P V (1-term: V single fp16), V via ldmatrix.trans ----
#pragma unroll
        for (int ks = 0; ks < 4; ks++) {
#pragma unroll
            for (int dp = 0; dp < 4; dp++) {
                const uint32_t va = st + A_VH +
                    (uint32_t)(((ks * 16 + (t4 & 1) * 8 + r8) * A_LDH +
                                dp * 16 + (t4 >> 1) * 8) * 2);
                uint32_t vh[4];
                LDSM4T(vh[0], vh[1], vh[2], vh[3], va);
#pragma unroll
                for (int half = 0; half < 2; half++) {
                    const int nt = dp * 2 + half, hf = half * 2;
                    MMA16816(o[nt], ph[ks], vh[hf], vh[hf + 1]);
                }
            }
        }
        __syncthreads();   // all warps done with this stage before re-fill
    }

    // ---- normalize + write [B, NH, T, HS] ----
    const float inv0 = 1.0f / l_i[0];
    const float inv1 = 1.0f / l_i[1];
    const int r0 = qt * 64 + wid * 16 + g;
#pragma unroll
    for (int nt = 0; nt < 8; nt++) {
        const int col = nt * 8 + 2 * t;
        *reinterpret_cast<float2*>(out + base + (size_t)r0 * HS_ + col) =
            make_float2(o[nt][0] * inv0, o[nt][1] * inv0);
        *reinterpret_cast<float2*>(out + base + (size_t)(r0 + 8) * HS_ + col) =
            make_float2(o[nt][2] * inv1, o[nt][3] * inv1);
    }
}

// ---------------------------------------------------------------------------
extern "C" void kernel_launch(void* const* d_in, const int* in_sizes, int n_in,
                              void* d_out, int out_size)
{
    (void)in_sizes; (void)n_in; (void)out_size;
    const float* x    = (const float*)d_in[0];
    const float* w    = (const float*)d_in[1];
    const float* bias = (const float*)d_in[2];
    float* out = (float*)d_out;

    conv_x_kernel<<<(M_ * K_ / 4 + 255) / 256, 256>>>(x);
    conv_w_kernel<<<((K_ / 4) * N3_ + 255) / 256, 256>>>(w);

    cudaFuncSetAttribute(qkv_gemm_tc,
                         cudaFuncAttributeMaxDynamicSharedMemorySize, GEMM_SMEM);
    dim3 g1(N3_ / 128, M_ / 128);    // (18, 32)
    qkv_gemm_tc<<<g1, 256, GEMM_SMEM>>>(bias);

    cudaFuncSetAttribute(attn_tc,
                         cudaFuncAttributeMaxDynamicSharedMemorySize, ATTN_SMEM);
    dim3 g2(T_ / 64, NH_, B_);       // (32, 12, 2)
    attn_tc<<<g2, 128, ATTN_SMEM>>>(out);
}

// round 16
// speedup vs baseline: 3.2286x; 1.1851x over previous
#include <cuda_runtime.h>
#include <cuda_fp16.h>
#include <math.h>
#include <stdint.h>

// Problem constants
constexpr int B_  = 2;
constexpr int T_  = 2048;
constexpr int C_  = 768;
constexpr int NH_ = 12;
constexpr int HS_ = 64;
constexpr int M_  = B_ * T_;      // 4096
constexpr int N3_ = 3 * C_;       // 2304
constexpr int K_  = C_;           // 768

typedef unsigned long long ull;

// ---------------------------------------------------------------------------
// PTX helpers (base-PTX only: legal at compute_103)
// ---------------------------------------------------------------------------
__device__ __forceinline__ uint32_t smem_u32(const void* p) {
    uint32_t a;
    asm("{ .reg .u64 t; cvta.to.shared.u64 t, %1; cvt.u32.u64 %0, t; }"
        : "=r"(a) : "l"(p));
    return a;
}

#define LDSM4(r0, r1, r2, r3, addr)                                          \
    asm volatile("ldmatrix.sync.aligned.m8n8.x4.shared.b16 {%0,%1,%2,%3}, [%4];" \
                 : "=r"(r0), "=r"(r1), "=r"(r2), "=r"(r3) : "r"(addr))

#define LDSM4T(r0, r1, r2, r3, addr)                                         \
    asm volatile("ldmatrix.sync.aligned.m8n8.x4.trans.shared.b16 {%0,%1,%2,%3}, [%4];" \
                 : "=r"(r0), "=r"(r1), "=r"(r2), "=r"(r3) : "r"(addr))

#define MMA16816(d, a, b0v, b1v)                                             \
    asm volatile("mma.sync.aligned.m16n8k16.row.col.f32.f16.f16.f32 "        \
                 "{%0,%1,%2,%3}, {%4,%5,%6,%7}, {%8,%9}, {%0,%1,%2,%3};"     \
                 : "+f"((d)[0]), "+f"((d)[1]), "+f"((d)[2]), "+f"((d)[3])    \
                 : "r"((a)[0]), "r"((a)[1]), "r"((a)[2]), "r"((a)[3]),       \
                   "r"(b0v), "r"(b1v))

#define CP_ASYNC16(dst, src)                                                 \
    asm volatile("cp.async.cg.shared.global [%0], [%1], 16;"                 \
                 :: "r"(dst), "l"(src) : "memory")
#define CP_COMMIT() asm volatile("cp.async.commit_group;" ::: "memory")
#define CP_WAIT0()  asm volatile("cp.async.wait_group 0;" ::: "memory")
#define CP_WAIT1()  asm volatile("cp.async.wait_group 1;" ::: "memory")

// fast 2^x
__device__ __forceinline__ float ex2(float x) {
    float y; asm("ex2.approx.ftz.f32 %0, %1;" : "=f"(y) : "f"(x)); return y;
}

// pack two f32 into f16x2 (x -> low half, y -> high half)
__device__ __forceinline__ uint32_t pack_h2(float x, float y) {
    uint32_t hp;
    asm("cvt.rn.f16x2.f32 %0, %1, %2;" : "=r"(hp) : "f"(y), "f"(x));
    return hp;
}
// hi/lo split: hi = f16(x),f16(y); lo = residuals
__device__ __forceinline__ uint32_t pack_h2_split(float x, float y, uint32_t& lo) {
    const uint32_t hp = pack_h2(x, y);
    const __half2 hh = *reinterpret_cast<const __half2*>(&hp);
    lo = pack_h2(x - __half2float(hh.x), y - __half2float(hh.y));
    return hp;
}

// ---------------------------------------------------------------------------
// Device scratch (all fp16)
// ---------------------------------------------------------------------------
constexpr size_t QKV_ELEMS = (size_t)B_ * NH_ * T_ * HS_;
__device__ __half g_qh[QKV_ELEMS];   // Q pre-scaled by 0.125*log2(e)
__device__ __half g_ql[QKV_ELEMS];   // Q residual
__device__ __half g_kh[QKV_ELEMS];   // K single fp16
__device__ __half g_vh[QKV_ELEMS];   // V single fp16
__device__ __half g_xh[(size_t)M_ * K_];
__device__ __half g_xl[(size_t)M_ * K_];
__device__ __half g_wth[(size_t)N3_ * K_];   // w transposed [N][K]
__device__ __half g_wtl[(size_t)N3_ * K_];   // residual (used for Q cols only)

// ---------------------------------------------------------------------------
// Convert kernels: fp32 -> fp16 hi/lo split (+ transpose for w)
// ---------------------------------------------------------------------------
__global__ __launch_bounds__(256) void conv_x_kernel(const float* __restrict__ x)
{
    const int idx = blockIdx.x * 256 + threadIdx.x;
    if (idx >= M_ * K_ / 4) return;
    float4 v = reinterpret_cast<const float4*>(x)[idx];
    float vv[4] = {v.x, v.y, v.z, v.w};
    ushort hs[4], ls[4];
#pragma unroll
    for (int e = 0; e < 4; e++) {
        __half h = __float2half(vv[e]);
        __half l = __float2half(vv[e] - __half2float(h));
        hs[e] = __half_as_ushort(h);
        ls[e] = __half_as_ushort(l);
    }
    *reinterpret_cast<ushort4*>(&g_xh[(size_t)idx * 4]) =
        make_ushort4(hs[0], hs[1], hs[2], hs[3]);
    *reinterpret_cast<ushort4*>(&g_xl[(size_t)idx * 4]) =
        make_ushort4(ls[0], ls[1], ls[2], ls[3]);
}

__global__ __launch_bounds__(256) void conv_w_kernel(const float* __restrict__ w)
{
    const int idx = blockIdx.x * 256 + threadIdx.x;
    if (idx >= (K_ / 4) * N3_) return;
    const int n  = idx % N3_;
    const int k4 = idx / N3_;
    ushort hs[4], ls[4];
#pragma unroll
    for (int e = 0; e < 4; e++) {
        float v = w[(size_t)(4 * k4 + e) * N3_ + n];
        __half h = __float2half(v);
        __half l = __float2half(v - __half2float(h));
        hs[e] = __half_as_ushort(h);
        ls[e] = __half_as_ushort(l);
    }
    *reinterpret_cast<ushort4*>(&g_wth[(size_t)n * K_ + 4 * k4]) =
        make_ushort4(hs[0], hs[1], hs[2], hs[3]);
    if (n < C_)   // residual only needed for Q columns
        *reinterpret_cast<ushort4*>(&g_wtl[(size_t)n * K_ + 4 * k4]) =
            make_ushort4(ls[0], ls[1], ls[2], ls[3]);
}

// ---------------------------------------------------------------------------
// Kernel: HMMA split GEMM (fp16).  Q columns: 3-term, split store.
// K/V columns: 2-term (xh*wh + xl*wh; w-residual dropped), single-fp16 store.
// CTA tile M=128 x N=128, 256 threads (8 warps, warp tile 32x64).
// ---------------------------------------------------------------------------
constexpr int CH  = 32;
constexpr int LDK = 40;
constexpr int NCH = K_ / CH;          // 24
constexpr int ARR_BYTES = 128 * LDK * 2;
constexpr int BUF_BYTES = 4 * ARR_BYTES;
constexpr int OFF_AH = 0;
constexpr int OFF_AL = ARR_BYTES;
constexpr int OFF_BH = 2 * ARR_BYTES;
constexpr int OFF_BL = 3 * ARR_BYTES;
constexpr int GEMM_SMEM = 2 * BUF_BYTES;          // 81920

__global__ __launch_bounds__(256, 2) void qkv_gemm_tc(const float* __restrict__ bias)
{
    extern __shared__ char smem[];
    const uint32_t sb = smem_u32(smem);
    const int tid  = threadIdx.x;
    const int wid  = tid >> 5, lane = tid & 31;
    const int wm   = wid & 3;
    const int wn   = wid >> 2;
    const int m0   = blockIdx.y * 128;
    const int n0   = blockIdx.x * 128;
    const int which = n0 / C_;          // 0=Q 1=K 2=V (uniform per CTA)
    const bool three = (which == 0);

    const int grow = tid >> 1;
    const int gpart = tid & 1;
    const __half* xh = g_xh + (size_t)(m0 + grow) * K_ + gpart * 16;
    const __half* xl = g_xl + (size_t)(m0 + grow) * K_ + gpart * 16;
    const __half* bh = g_wth + (size_t)(n0 + grow) * K_ + gpart * 16;
    const __half* bl = g_wtl + (size_t)(n0 + grow) * K_ + gpart * 16;
    const uint32_t sdst = sb + (uint32_t)((grow * LDK + gpart * 16) * 2);

    auto issue_loads = [&](int c, int buf) {
        const uint32_t d0 = sdst + buf * BUF_BYTES;
        const int ko = c * CH;
#pragma unroll
        for (int i = 0; i < 2; i++) {
            CP_ASYNC16(d0 + OFF_AH + i * 16, xh + ko + i * 8);
            CP_ASYNC16(d0 + OFF_AL + i * 16, xl + ko + i * 8);
            CP_ASYNC16(d0 + OFF_BH + i * 16, bh + ko + i * 8);
            if (three)
                CP_ASYNC16(d0 + OFF_BL + i * 16, bl + ko + i * 8);
        }
    };

    const int t4 = lane >> 3, r8 = lane & 7;
    const int a_moff = (t4 & 1) * 8, a_koff = (t4 >> 1) * 8;
    const int b_noff = (t4 >> 1) * 8, b_koff = (t4 & 1) * 8;

    float d[2][8][4];
#pragma unroll
    for (int mt = 0; mt < 2; mt++)
#pragma unroll
        for (int nt = 0; nt < 8; nt++)
#pragma unroll
            for (int e = 0; e < 4; e++) d[mt][nt][e] = 0.0f;

    issue_loads(0, 0);
    CP_COMMIT();

    for (int c = 0; c < NCH; c++) {
        CP_WAIT0();
        __syncthreads();
        if (c + 1 < NCH) { issue_loads(c + 1, (c + 1) & 1); }
        CP_COMMIT();

        const uint32_t bufb = sb + (uint32_t)((c & 1) * BUF_BYTES);
#pragma unroll
        for (int ks = 0; ks < 2; ks++) {
            uint32_t ah[2][4], al[2][4];
#pragma unroll
            for (int mt = 0; mt < 2; mt++) {
                const uint32_t ad = bufb + OFF_AH +
                    (uint32_t)(((wm * 32 + mt * 16 + a_moff + r8) * LDK +
                                ks * 16 + a_koff) * 2);
                LDSM4(ah[mt][0], ah[mt][1], ah[mt][2], ah[mt][3], ad);
                LDSM4(al[mt][0], al[mt][1], al[mt][2], al[mt][3],
                      ad + (OFF_AL - OFF_AH));
            }
#pragma unroll
            for (int np = 0; np < 4; np++) {
                const uint32_t bd = bufb + OFF_BH +
                    (uint32_t)(((wn * 64 + np * 16 + b_noff + r8) * LDK +
                                ks * 16 + b_koff) * 2);
                uint32_t bhf[4], blf[4];
                LDSM4(bhf[0], bhf[1], bhf[2], bhf[3], bd);
                if (three)
                    LDSM4(blf[0], blf[1], blf[2], blf[3], bd + (OFF_BL - OFF_BH));
#pragma unroll
                for (int mt = 0; mt < 2; mt++)
#pragma unroll
                    for (int half = 0; half < 2; half++) {
                        const int nt = np * 2 + half, hf = half * 2;
                        MMA16816(d[mt][nt], ah[mt], bhf[hf], bhf[hf + 1]);
                        MMA16816(d[mt][nt], al[mt], bhf[hf], bhf[hf + 1]);
                        if (three)
                            MMA16816(d[mt][nt], ah[mt], blf[hf], blf[hf + 1]);
                    }
            }
        }
    }

    // Epilogue: bias (+q scale incl. log2(e)), store
    const int g = lane >> 2, tig = lane & 3;
    const int nrel0 = n0 - which * C_;
    const float qscale =
        (which == 0) ? 0.125f * 1.4426950408889634f : 1.0f;
    __half* mh = (which == 0) ? g_qh : (which == 1) ? g_kh : g_vh;
#pragma unroll
    for (int mt = 0; mt < 2; mt++) {
        const int m = m0 + wm * 32 + mt * 16 + g;
#pragma unroll
        for (int rr = 0; rr < 2; rr++) {
            const int mr = m + rr * 8;
            const int bb = mr >> 11;
            const int t  = mr & 2047;
#pragma unroll
            for (int nt = 0; nt < 8; nt++) {
                const int nrel = nrel0 + wn * 64 + nt * 8 + 2 * tig;
                const int head = nrel >> 6;
                const int dcol = nrel & 63;
                const float v0 =
                    (d[mt][nt][2 * rr + 0] + bias[which * C_ + nrel]) * qscale;
                const float v1 =
                    (d[mt][nt][2 * rr + 1] + bias[which * C_ + nrel + 1]) * qscale;
                const size_t idx = (((size_t)bb * NH_ + head) * T_ + t) * HS_ + dcol;
                if (which == 0) {
                    uint32_t lp;
                    const uint32_t hp = pack_h2_split(v0, v1, lp);
                    *reinterpret_cast<uint32_t*>(mh + idx) = hp;
                    *reinterpret_cast<uint32_t*>(g_ql + idx) = lp;
                } else {
                    *reinterpret_cast<uint32_t*>(mh + idx) = pack_h2(v0, v1);
                }
            }
        }
    }
}

// ---------------------------------------------------------------------------
// Kernel: tensor-core flash attention (fp16).
// CTA = (b, h, 64-row q-tile), 128 threads (4 warps x m16). BC=64 keys.
// S = (qh+ql) * kh : 2-term QK (K single fp16). softmax base-2. P single fp16.
// O += P V : 1-term (V single fp16). 3-stage KV pipeline, ONE barrier/iter.
// ---------------------------------------------------------------------------
constexpr int A_LDH   = 72;                          // halves per smem row
constexpr int A_ARR   = 64 * A_LDH * 2;              // 9216 B per 64x64 tile
constexpr int A_KH = 0, A_VH = A_ARR;
constexpr int A_STAGEB = 2 * A_ARR;                  // 18432
constexpr int ATTN_SMEM = 3 * A_STAGEB;              // 55296

__global__ __launch_bounds__(128, 3) void attn_tc(float* __restrict__ out)
{
    extern __shared__ char smc[];
    const uint32_t sb = smem_u32(smc);
    const int tid  = threadIdx.x;
    const int wid  = tid >> 5, lane = tid & 31;
    const int g    = lane >> 2, t = lane & 3;
    const int t4   = lane >> 3, r8 = lane & 7;
    const int qt   = (T_ / 64) - 1 - blockIdx.x;     // heavy tiles first
    const int h    = blockIdx.y;
    const int b    = blockIdx.z;
    const size_t base = ((size_t)b * NH_ + h) * T_ * HS_;

    // ---- async load geometry: thread -> (row = tid/2, 32-half chunk = tid&1)
    const int lrow = tid >> 1;
    const int lcol = (tid & 1) * 32;
    const uint32_t sdst = (uint32_t)((lrow * A_LDH + lcol) * 2);

    auto issue_kv = [&](int j, int s) {
        const uint32_t st = sb + s * A_STAGEB;
        const size_t src = base + (size_t)(j * 64 + lrow) * HS_ + lcol;
#pragma unroll
        for (int i = 0; i < 4; i++) {
            CP_ASYNC16(st + A_KH + sdst + i * 16, g_kh + src + i * 8);
            CP_ASYNC16(st + A_VH + sdst + i * 16, g_vh + src + i * 8);
        }
    };

    // prologue group G0: Q (into stage 2) + KV block 0 (stage 0)
    {
        const __half* qh = g_qh + base + (size_t)(qt * 64 + lrow) * HS_ + lcol;
        const __half* ql = g_ql + base + (size_t)(qt * 64 + lrow) * HS_ + lcol;
        const uint32_t st2 = sb + 2 * A_STAGEB;
#pragma unroll
        for (int i = 0; i < 4; i++) {
            CP_ASYNC16(st2 + A_KH + sdst + i * 16, qh + i * 8);
            CP_ASYNC16(st2 + A_VH + sdst + i * 16, ql + i * 8);
        }
        issue_kv(0, 0);
        CP_COMMIT();                       // G0
        if (qt >= 1) { issue_kv(1, 1); CP_COMMIT(); }   // G1
    }

    // fragment geometry
    const int a_moff = (t4 & 1) * 8, a_koff = (t4 >> 1) * 8;
    const int b_noff = (t4 >> 1) * 8, b_koff = (t4 & 1) * 8;

    // ---- prologue: wait G0, extract Q fragments, free stage 2 ----
    uint32_t qhf[4][4], qlf[4][4];
    if (qt >= 1) { CP_WAIT1(); } else { CP_WAIT0(); }
    __syncthreads();
#pragma unroll
    for (int ks = 0; ks < 4; ks++) {
        const uint32_t qa = sb + 2 * A_STAGEB +
            (uint32_t)(((wid * 16 + a_moff + r8) * A_LDH + ks * 16 + a_koff) * 2);
        LDSM4(qhf[ks][0], qhf[ks][1], qhf[ks][2], qhf[ks][3], qa);
        LDSM4(qlf[ks][0], qlf[ks][1], qlf[ks][2], qlf[ks][3], qa + A_ARR);
    }
    __syncthreads();   // Q read done; stage 2 reusable

    float o[8][4];
#pragma unroll
    for (int nt = 0; nt < 8; nt++)
#pragma unroll
        for (int e = 0; e < 4; e++) o[nt][e] = 0.0f;
    float m_i[2] = {-INFINITY, -INFINITY};
    float l_i[2] = {0.0f, 0.0f};

    for (int j = 0; j <= qt; j++) {
        if (j < qt) { CP_WAIT1(); } else { CP_WAIT0(); }
        __syncthreads();   // stage j visible; all warps past iter j-1
        if (j + 2 <= qt) { issue_kv(j + 2, (j + 2) % 3); CP_COMMIT(); }

        const uint32_t st = sb + (j % 3) * A_STAGEB;

        // ---- S = (qh + ql) * kh  (2-term, K single fp16) ----
        float s[8][4];
#pragma unroll
        for (int nt = 0; nt < 8; nt++)
#pragma unroll
            for (int e = 0; e < 4; e++) s[nt][e] = 0.0f;

#pragma unroll
        for (int ks = 0; ks < 4; ks++) {
#pragma unroll
            for (int np = 0; np < 4; np++) {
                const uint32_t ka = st + A_KH +
                    (uint32_t)(((np * 16 + b_noff + r8) * A_LDH +
                                ks * 16 + b_koff) * 2);
                uint32_t kh[4];
                LDSM4(kh[0], kh[1], kh[2], kh[3], ka);
#pragma unroll
                for (int half = 0; half < 2; half++) {
                    const int nt = np * 2 + half, hf = half * 2;
                    MMA16816(s[nt], qhf[ks], kh[hf], kh[hf + 1]);
                    MMA16816(s[nt], qlf[ks], kh[hf], kh[hf + 1]);
                }
            }
        }

        // ---- causal mask on diagonal block ----
        if (j == qt) {
            const int r0 = wid * 16 + g;
#pragma unroll
            for (int nt = 0; nt < 8; nt++) {
                const int c0 = nt * 8 + 2 * t;
                if (c0 > r0)          s[nt][0] = -INFINITY;
                if (c0 + 1 > r0)      s[nt][1] = -INFINITY;
                if (c0 > r0 + 8)      s[nt][2] = -INFINITY;
                if (c0 + 1 > r0 + 8)  s[nt][3] = -INFINITY;
            }
        }

        // ---- online softmax (base-2 domain) on fragments ----
        float mx0 = -INFINITY, mx1 = -INFINITY;
#pragma unroll
        for (int nt = 0; nt < 8; nt++) {
            mx0 = fmaxf(mx0, fmaxf(s[nt][0], s[nt][1]));
            mx1 = fmaxf(mx1, fmaxf(s[nt][2], s[nt][3]));
        }
        mx0 = fmaxf(mx0, __shfl_xor_sync(0xffffffffu, mx0, 1));
        mx0 = fmaxf(mx0, __shfl_xor_sync(0xffffffffu, mx0, 2));
        mx1 = fmaxf(mx1, __shfl_xor_sync(0xffffffffu, mx1, 1));
        mx1 = fmaxf(mx1, __shfl_xor_sync(0xffffffffu, mx1, 2));
        const float mn0 = fmaxf(m_i[0], mx0);
        const float mn1 = fmaxf(m_i[1], mx1);
        const float corr0 = ex2(m_i[0] - mn0);
        const float corr1 = ex2(m_i[1] - mn1);
        m_i[0] = mn0; m_i[1] = mn1;

        float sum0 = 0.0f, sum1 = 0.0f;
#pragma unroll
        for (int nt = 0; nt < 8; nt++) {
            s[nt][0] = ex2(s[nt][0] - mn0); sum0 += s[nt][0];
            s[nt][1] = ex2(s[nt][1] - mn0); sum0 += s[nt][1];
            s[nt][2] = ex2(s[nt][2] - mn1); sum1 += s[nt][2];
            s[nt][3] = ex2(s[nt][3] - mn1); sum1 += s[nt][3];
            o[nt][0] *= corr0; o[nt][1] *= corr0;
            o[nt][2] *= corr1; o[nt][3] *= corr1;
        }
        sum0 += __shfl_xor_sync(0xffffffffu, sum0, 1);
        sum0 += __shfl_xor_sync(0xffffffffu, sum0, 2);
        sum1 += __shfl_xor_sync(0xffffffffu, sum1, 1);
        sum1 += __shfl_xor_sync(0xffffffffu, sum1, 2);
        l_i[0] = l_i[0] * corr0 + sum0;
        l_i[1] = l_i[1] * corr1 + sum1;

        // ---- P -> A fragments (single fp16) ----
        uint32_t ph[4][4];
#pragma unroll
        for (int ks = 0; ks < 4; ks++) {
            ph[ks][0] = pack_h2(s[2 * ks][0],     s[2 * ks][1]);
            ph[ks][1] = pack_h2(s[2 * ks][2],     s[2 * ks][3]);
            ph[ks][2] = pack_h2(s[2 * ks + 1][0], s[2 * ks + 1][1]);
            ph[ks][3] = pack_h2(s[2 * ks + 1][2], s[2 * ks + 1][3]);
        }

        // ---- O += P V (1-term), V via ldmatrix.trans ----
#pragma unroll
        for (int ks = 0; ks < 4; ks++) {
#pragma unroll
            for (int dp = 0; dp < 4; dp++) {
                const uint32_t va = st + A_VH +
                    (uint32_t)(((ks * 16 + (t4 & 1) * 8 + r8) * A_LDH +
                                dp * 16 + (t4 >> 1) * 8) * 2);
                uint32_t vh[4];
                LDSM4T(vh[0], vh[1], vh[2], vh[3], va);
#pragma unroll
                for (int half = 0; half < 2; half++) {
                    const int nt = dp * 2 + half, hf = half * 2;
                    MMA16816(o[nt], ph[ks], vh[hf], vh[hf + 1]);
                }
            }
        }
    }

    // ---- normalize + write [B, NH, T, HS] ----
    const float inv0 = 1.0f / l_i[0];
    const float inv1 = 1.0f / l_i[1];
    const int r0 = qt * 64 + wid * 16 + g;
#pragma unroll
    for (int nt = 0; nt < 8; nt++) {
        const int col = nt * 8 + 2 * t;
        *reinterpret_cast<float2*>(out + base + (size_t)r0 * HS_ + col) =
            make_float2(o[nt][0] * inv0, o[nt][1] * inv0);
        *reinterpret_cast<float2*>(out + base + (size_t)(r0 + 8) * HS_ + col) =
            make_float2(o[nt][2] * inv1, o[nt][3] * inv1);
    }
}

// ---------------------------------------------------------------------------
extern "C" void kernel_launch(void* const* d_in, const int* in_sizes, int n_in,
                              void* d_out, int out_size)
{
    (void)in_sizes; (void)n_in; (void)out_size;
    const float* x    = (const float*)d_in[0];
    const float* w    = (const float*)d_in[1];
    const float* bias = (const float*)d_in[2];
    float* out = (float*)d_out;

    conv_x_kernel<<<(M_ * K_ / 4 + 255) / 256, 256>>>(x);
    conv_w_kernel<<<((K_ / 4) * N3_ + 255) / 256, 256>>>(w);

    cudaFuncSetAttribute(qkv_gemm_tc,
                         cudaFuncAttributeMaxDynamicSharedMemorySize, GEMM_SMEM);
    dim3 g1(N3_ / 128, M_ / 128);    // (18, 32)
    qkv_gemm_tc<<<g1, 256, GEMM_SMEM>>>(bias);

    cudaFuncSetAttribute(attn_tc,
                         cudaFuncAttributeMaxDynamicSharedMemorySize, ATTN_SMEM);
    dim3 g2(T_ / 64, NH_, B_);       // (32, 12, 2)
    attn_tc<<<g2, 128, ATTN_SMEM>>>(out);
}

// round 17
// speedup vs baseline: 3.6698x; 1.1367x over previous
#include <cuda_runtime.h>
#include <cuda_fp16.h>
#include <math.h>
#include <stdint.h>

// Problem constants
constexpr int B_  = 2;
constexpr int T_  = 2048;
constexpr int C_  = 768;
constexpr int NH_ = 12;
constexpr int HS_ = 64;
constexpr int M_  = B_ * T_;      // 4096
constexpr int N3_ = 3 * C_;       // 2304
constexpr int K_  = C_;           // 768

typedef unsigned long long ull;

// ---------------------------------------------------------------------------
// PTX helpers (base-PTX only: legal at compute_103)
// ---------------------------------------------------------------------------
__device__ __forceinline__ uint32_t smem_u32(const void* p) {
    uint32_t a;
    asm("{ .reg .u64 t; cvta.to.shared.u64 t, %1; cvt.u32.u64 %0, t; }"
        : "=r"(a) : "l"(p));
    return a;
}

#define LDSM4(r0, r1, r2, r3, addr)                                          \
    asm volatile("ldmatrix.sync.aligned.m8n8.x4.shared.b16 {%0,%1,%2,%3}, [%4];" \
                 : "=r"(r0), "=r"(r1), "=r"(r2), "=r"(r3) : "r"(addr))

#define LDSM4T(r0, r1, r2, r3, addr)                                         \
    asm volatile("ldmatrix.sync.aligned.m8n8.x4.trans.shared.b16 {%0,%1,%2,%3}, [%4];" \
                 : "=r"(r0), "=r"(r1), "=r"(r2), "=r"(r3) : "r"(addr))

#define MMA16816(d, a, b0v, b1v)                                             \
    asm volatile("mma.sync.aligned.m16n8k16.row.col.f32.f16.f16.f32 "        \
                 "{%0,%1,%2,%3}, {%4,%5,%6,%7}, {%8,%9}, {%0,%1,%2,%3};"     \
                 : "+f"((d)[0]), "+f"((d)[1]), "+f"((d)[2]), "+f"((d)[3])    \
                 : "r"((a)[0]), "r"((a)[1]), "r"((a)[2]), "r"((a)[3]),       \
                   "r"(b0v), "r"(b1v))

#define CP_ASYNC16(dst, src)                                                 \
    asm volatile("cp.async.cg.shared.global [%0], [%1], 16;"                 \
                 :: "r"(dst), "l"(src) : "memory")
#define CP_COMMIT() asm volatile("cp.async.commit_group;" ::: "memory")
#define CP_WAIT0()  asm volatile("cp.async.wait_group 0;" ::: "memory")
#define CP_WAIT1()  asm volatile("cp.async.wait_group 1;" ::: "memory")

// fast 2^x
__device__ __forceinline__ float ex2(float x) {
    float y; asm("ex2.approx.ftz.f32 %0, %1;" : "=f"(y) : "f"(x)); return y;
}

// pack two f32 into f16x2 (x -> low half, y -> high half)
__device__ __forceinline__ uint32_t pack_h2(float x, float y) {
    uint32_t hp;
    asm("cvt.rn.f16x2.f32 %0, %1, %2;" : "=r"(hp) : "f"(y), "f"(x));
    return hp;
}
// hi/lo split: hi = f16(x),f16(y); lo = residuals
__device__ __forceinline__ uint32_t pack_h2_split(float x, float y, uint32_t& lo) {
    const uint32_t hp = pack_h2(x, y);
    const __half2 hh = *reinterpret_cast<const __half2*>(&hp);
    lo = pack_h2(x - __half2float(hh.x), y - __half2float(hh.y));
    return hp;
}

// ---------------------------------------------------------------------------
// Device scratch (all fp16)
// ---------------------------------------------------------------------------
constexpr size_t QKV_ELEMS = (size_t)B_ * NH_ * T_ * HS_;
__device__ __half g_qh[QKV_ELEMS];   // Q pre-scaled by 0.125*log2(e)
__device__ __half g_ql[QKV_ELEMS];   // Q residual
__device__ __half g_kh[QKV_ELEMS];   // K single fp16
__device__ __half g_vh[QKV_ELEMS];   // V single fp16
__device__ __half g_xh[(size_t)M_ * K_];
__device__ __half g_xl[(size_t)M_ * K_];
__device__ __half g_wth[(size_t)N3_ * K_];   // w transposed [N][K], single fp16

// ---------------------------------------------------------------------------
// Convert kernels: x -> fp16 hi/lo split; w -> fp16 transposed
// ---------------------------------------------------------------------------
__global__ __launch_bounds__(256) void conv_x_kernel(const float* __restrict__ x)
{
    const int idx = blockIdx.x * 256 + threadIdx.x;
    if (idx >= M_ * K_ / 4) return;
    float4 v = reinterpret_cast<const float4*>(x)[idx];
    float vv[4] = {v.x, v.y, v.z, v.w};
    ushort hs[4], ls[4];
#pragma unroll
    for (int e = 0; e < 4; e++) {
        __half h = __float2half(vv[e]);
        __half l = __float2half(vv[e] - __half2float(h));
        hs[e] = __half_as_ushort(h);
        ls[e] = __half_as_ushort(l);
    }
    *reinterpret_cast<ushort4*>(&g_xh[(size_t)idx * 4]) =
        make_ushort4(hs[0], hs[1], hs[2], hs[3]);
    *reinterpret_cast<ushort4*>(&g_xl[(size_t)idx * 4]) =
        make_ushort4(ls[0], ls[1], ls[2], ls[3]);
}

__global__ __launch_bounds__(256) void conv_w_kernel(const float* __restrict__ w)
{
    const int idx = blockIdx.x * 256 + threadIdx.x;
    if (idx >= (K_ / 4) * N3_) return;
    const int n  = idx % N3_;
    const int k4 = idx / N3_;
    ushort hs[4];
#pragma unroll
    for (int e = 0; e < 4; e++)
        hs[e] = __half_as_ushort(__float2half(w[(size_t)(4 * k4 + e) * N3_ + n]));
    *reinterpret_cast<ushort4*>(&g_wth[(size_t)n * K_ + 4 * k4]) =
        make_ushort4(hs[0], hs[1], hs[2], hs[3]);
}

// ---------------------------------------------------------------------------
// Kernel: HMMA 2-term GEMM (fp16):  out = (xh + xl) * wh  (+ bias).
// Q columns: hi/lo split store.  K/V: single-fp16 store.
// CTA tile M=128 x N=128, 256 threads (8 warps, warp tile 32x64).
// K-chunk 64 (12 iterations), 3 smem arrays, double-buffered, 2 CTAs/SM.
// ---------------------------------------------------------------------------
constexpr int CH  = 64;
constexpr int LDK = 72;               // halves per smem row (144B, 16B-aligned)
constexpr int NCH = K_ / CH;          // 12
constexpr int ARR_BYTES = 128 * LDK * 2;          // 18432
constexpr int OFF_AH = 0;
constexpr int OFF_AL = ARR_BYTES;
constexpr int OFF_BH = 2 * ARR_BYTES;
constexpr int BUF_BYTES = 3 * ARR_BYTES;          // 55296
constexpr int GEMM_SMEM = 2 * BUF_BYTES;          // 110592

__global__ __launch_bounds__(256, 2) void qkv_gemm_tc(const float* __restrict__ bias)
{
    extern __shared__ char smem[];
    const uint32_t sb = smem_u32(smem);
    const int tid  = threadIdx.x;
    const int wid  = tid >> 5, lane = tid & 31;
    const int wm   = wid & 3;
    const int wn   = wid >> 2;
    const int m0   = blockIdx.y * 128;
    const int n0   = blockIdx.x * 128;
    const int which = n0 / C_;          // 0=Q 1=K 2=V (uniform per CTA)

    // global-load role: row = tid/2 (0..127), half-row = tid&1 (32 halves)
    const int grow  = tid >> 1;
    const int gpart = tid & 1;
    const __half* xh = g_xh + (size_t)(m0 + grow) * K_ + gpart * 32;
    const __half* xl = g_xl + (size_t)(m0 + grow) * K_ + gpart * 32;
    const __half* bh = g_wth + (size_t)(n0 + grow) * K_ + gpart * 32;
    const uint32_t sdst = sb + (uint32_t)((grow * LDK + gpart * 32) * 2);

    auto issue_loads = [&](int c, int buf) {
        const uint32_t d0 = sdst + buf * BUF_BYTES;
        const int ko = c * CH;
#pragma unroll
        for (int i = 0; i < 4; i++) {
            CP_ASYNC16(d0 + OFF_AH + i * 16, xh + ko + i * 8);
            CP_ASYNC16(d0 + OFF_AL + i * 16, xl + ko + i * 8);
            CP_ASYNC16(d0 + OFF_BH + i * 16, bh + ko + i * 8);
        }
    };

    const int t4 = lane >> 3, r8 = lane & 7;
    const int a_moff = (t4 & 1) * 8, a_koff = (t4 >> 1) * 8;
    const int b_noff = (t4 >> 1) * 8, b_koff = (t4 & 1) * 8;

    float d[2][8][4];
#pragma unroll
    for (int mt = 0; mt < 2; mt++)
#pragma unroll
        for (int nt = 0; nt < 8; nt++)
#pragma unroll
            for (int e = 0; e < 4; e++) d[mt][nt][e] = 0.0f;

    issue_loads(0, 0);
    CP_COMMIT();

    for (int c = 0; c < NCH; c++) {
        CP_WAIT0();
        __syncthreads();
        if (c + 1 < NCH) { issue_loads(c + 1, (c + 1) & 1); }
        CP_COMMIT();

        const uint32_t bufb = sb + (uint32_t)((c & 1) * BUF_BYTES);
#pragma unroll
        for (int ks = 0; ks < 4; ks++) {
            uint32_t ah[2][4], al[2][4];
#pragma unroll
            for (int mt = 0; mt < 2; mt++) {
                const uint32_t ad = bufb + OFF_AH +
                    (uint32_t)(((wm * 32 + mt * 16 + a_moff + r8) * LDK +
                                ks * 16 + a_koff) * 2);
                LDSM4(ah[mt][0], ah[mt][1], ah[mt][2], ah[mt][3], ad);
                LDSM4(al[mt][0], al[mt][1], al[mt][2], al[mt][3],
                      ad + (OFF_AL - OFF_AH));
            }
#pragma unroll
            for (int np = 0; np < 4; np++) {
                const uint32_t bd = bufb + OFF_BH +
                    (uint32_t)(((wn * 64 + np * 16 + b_noff + r8) * LDK +
                                ks * 16 + b_koff) * 2);
                uint32_t bhf[4];
                LDSM4(bhf[0], bhf[1], bhf[2], bhf[3], bd);
#pragma unroll
                for (int mt = 0; mt < 2; mt++)
#pragma unroll
                    for (int half = 0; half < 2; half++) {
                        const int nt = np * 2 + half, hf = half * 2;
                        MMA16816(d[mt][nt], ah[mt], bhf[hf], bhf[hf + 1]);
                        MMA16816(d[mt][nt], al[mt], bhf[hf], bhf[hf + 1]);
                    }
            }
        }
    }

    // Epilogue: bias (+q scale incl. log2(e)), store
    const int g = lane >> 2, tig = lane & 3;
    const int nrel0 = n0 - which * C_;
    const float qscale =
        (which == 0) ? 0.125f * 1.4426950408889634f : 1.0f;
    __half* mh = (which == 0) ? g_qh : (which == 1) ? g_kh : g_vh;
#pragma unroll
    for (int mt = 0; mt < 2; mt++) {
        const int m = m0 + wm * 32 + mt * 16 + g;
#pragma unroll
        for (int rr = 0; rr < 2; rr++) {
            const int mr = m + rr * 8;
            const int bb = mr >> 11;
            const int t  = mr & 2047;
#pragma unroll
            for (int nt = 0; nt < 8; nt++) {
                const int nrel = nrel0 + wn * 64 + nt * 8 + 2 * tig;
                const int head = nrel >> 6;
                const int dcol = nrel & 63;
                const float v0 =
                    (d[mt][nt][2 * rr + 0] + bias[which * C_ + nrel]) * qscale;
                const float v1 =
                    (d[mt][nt][2 * rr + 1] + bias[which * C_ + nrel + 1]) * qscale;
                const size_t idx = (((size_t)bb * NH_ + head) * T_ + t) * HS_ + dcol;
                if (which == 0) {
                    uint32_t lp;
                    const uint32_t hp = pack_h2_split(v0, v1, lp);
                    *reinterpret_cast<uint32_t*>(mh + idx) = hp;
                    *reinterpret_cast<uint32_t*>(g_ql + idx) = lp;
                } else {
                    *reinterpret_cast<uint32_t*>(mh + idx) = pack_h2(v0, v1);
                }
            }
        }
    }
}

// ---------------------------------------------------------------------------
// Kernel: tensor-core flash attention (fp16) — unchanged from R16.
// CTA = (b, h, 64-row q-tile), 128 threads (4 warps x m16). BC=64 keys.
// S = (qh+ql) * kh : 2-term QK. softmax base-2. P single fp16.
// O += P V : 1-term. 3-stage KV pipeline, ONE barrier/iter.
// ---------------------------------------------------------------------------
constexpr int A_LDH   = 72;                          // halves per smem row
constexpr int A_ARR   = 64 * A_LDH * 2;              // 9216 B per 64x64 tile
constexpr int A_KH = 0, A_VH = A_ARR;
constexpr int A_STAGEB = 2 * A_ARR;                  // 18432
constexpr int ATTN_SMEM = 3 * A_STAGEB;              // 55296

__global__ __launch_bounds__(128, 3) void attn_tc(float* __restrict__ out)
{
    extern __shared__ char smc[];
    const uint32_t sb = smem_u32(smc);
    const int tid  = threadIdx.x;
    const int wid  = tid >> 5, lane = tid & 31;
    const int g    = lane >> 2, t = lane & 3;
    const int t4   = lane >> 3, r8 = lane & 7;
    const int qt   = (T_ / 64) - 1 - blockIdx.x;     // heavy tiles first
    const int h    = blockIdx.y;
    const int b    = blockIdx.z;
    const size_t base = ((size_t)b * NH_ + h) * T_ * HS_;

    // ---- async load geometry: thread -> (row = tid/2, 32-half chunk = tid&1)
    const int lrow = tid >> 1;
    const int lcol = (tid & 1) * 32;
    const uint32_t sdst = (uint32_t)((lrow * A_LDH + lcol) * 2);

    auto issue_kv = [&](int j, int s) {
        const uint32_t st = sb + s * A_STAGEB;
        const size_t src = base + (size_t)(j * 64 + lrow) * HS_ + lcol;
#pragma unroll
        for (int i = 0; i < 4; i++) {
            CP_ASYNC16(st + A_KH + sdst + i * 16, g_kh + src + i * 8);
            CP_ASYNC16(st + A_VH + sdst + i * 16, g_vh + src + i * 8);
        }
    };

    // prologue group G0: Q (into stage 2) + KV block 0 (stage 0)
    {
        const __half* qh = g_qh + base + (size_t)(qt * 64 + lrow) * HS_ + lcol;
        const __half* ql = g_ql + base + (size_t)(qt * 64 + lrow) * HS_ + lcol;
        const uint32_t st2 = sb + 2 * A_STAGEB;
#pragma unroll
        for (int i = 0; i < 4; i++) {
            CP_ASYNC16(st2 + A_KH + sdst + i * 16, qh + i * 8);
            CP_ASYNC16(st2 + A_VH + sdst + i * 16, ql + i * 8);
        }
        issue_kv(0, 0);
        CP_COMMIT();                       // G0
        if (qt >= 1) { issue_kv(1, 1); CP_COMMIT(); }   // G1
    }

    // fragment geometry
    const int a_moff = (t4 & 1) * 8, a_koff = (t4 >> 1) * 8;
    const int b_noff = (t4 >> 1) * 8, b_koff = (t4 & 1) * 8;

    // ---- prologue: wait G0, extract Q fragments, free stage 2 ----
    uint32_t qhf[4][4], qlf[4][4];
    if (qt >= 1) { CP_WAIT1(); } else { CP_WAIT0(); }
    __syncthreads();
#pragma unroll
    for (int ks = 0; ks < 4; ks++) {
        const uint32_t qa = sb + 2 * A_STAGEB +
            (uint32_t)(((wid * 16 + a_moff + r8) * A_LDH + ks * 16 + a_koff) * 2);
        LDSM4(qhf[ks][0], qhf[ks][1], qhf[ks][2], qhf[ks][3], qa);
        LDSM4(qlf[ks][0], qlf[ks][1], qlf[ks][2], qlf[ks][3], qa + A_ARR);
    }
    __syncthreads();   // Q read done; stage 2 reusable

    float o[8][4];
#pragma unroll
    for (int nt = 0; nt < 8; nt++)
#pragma unroll
        for (int e = 0; e < 4; e++) o[nt][e] = 0.0f;
    float m_i[2] = {-INFINITY, -INFINITY};
    float l_i[2] = {0.0f, 0.0f};

    for (int j = 0; j <= qt; j++) {
        if (j < qt) { CP_WAIT1(); } else { CP_WAIT0(); }
        __syncthreads();   // stage j visible; all warps past iter j-1
        if (j + 2 <= qt) { issue_kv(j + 2, (j + 2) % 3); CP_COMMIT(); }

        const uint32_t st = sb + (j % 3) * A_STAGEB;

        // ---- S = (qh + ql) * kh  (2-term, K single fp16) ----
        float s[8][4];
#pragma unroll
        for (int nt = 0; nt < 8; nt++)
#pragma unroll
            for (int e = 0; e < 4; e++) s[nt][e] = 0.0f;

#pragma unroll
        for (int ks = 0; ks < 4; ks++) {
#pragma unroll
            for (int np = 0; np < 4; np++) {
                const uint32_t ka = st + A_KH +
                    (uint32_t)(((np * 16 + b_noff + r8) * A_LDH +
                                ks * 16 + b_koff) * 2);
                uint32_t kh[4];
                LDSM4(kh[0], kh[1], kh[2], kh[3], ka);
#pragma unroll
                for (int half = 0; half < 2; half++) {
                    const int nt = np * 2 + half, hf = half * 2;
                    MMA16816(s[nt], qhf[ks], kh[hf], kh[hf + 1]);
                    MMA16816(s[nt], qlf[ks], kh[hf], kh[hf + 1]);
                }
            }
        }

        // ---- causal mask on diagonal block ----
        if (j == qt) {
            const int r0 = wid * 16 + g;
#pragma unroll
            for (int nt = 0; nt < 8; nt++) {
                const int c0 = nt * 8 + 2 * t;
                if (c0 > r0)          s[nt][0] = -INFINITY;
                if (c0 + 1 > r0)      s[nt][1] = -INFINITY;
                if (c0 > r0 + 8)      s[nt][2] = -INFINITY;
                if (c0 + 1 > r0 + 8)  s[nt][3] = -INFINITY;
            }
        }

        // ---- online softmax (base-2 domain) on fragments ----
        float mx0 = -INFINITY, mx1 = -INFINITY;
#pragma unroll
        for (int nt = 0; nt < 8; nt++) {
            mx0 = fmaxf(mx0, fmaxf(s[nt][0], s[nt][1]));
            mx1 = fmaxf(mx1, fmaxf(s[nt][2], s[nt][3]));
        }
        mx0 = fmaxf(mx0, __shfl_xor_sync(0xffffffffu, mx0, 1));
        mx0 = fmaxf(mx0, __shfl_xor_sync(0xffffffffu, mx0, 2));
        mx1 = fmaxf(mx1, __shfl_xor_sync(0xffffffffu, mx1, 1));
        mx1 = fmaxf(mx1, __shfl_xor_sync(0xffffffffu, mx1, 2));
        const float mn0 = fmaxf(m_i[0], mx0);
        const float mn1 = fmaxf(m_i[1], mx1);
        const float corr0 = ex2(m_i[0] - mn0);
        const float corr1 = ex2(m_i[1] - mn1);
        m_i[0] = mn0; m_i[1] = mn1;

        float sum0 = 0.0f, sum1 = 0.0f;
#pragma unroll
        for (int nt = 0; nt < 8; nt++) {
            s[nt][0] = ex2(s[nt][0] - mn0); sum0 += s[nt][0];
            s[nt][1] = ex2(s[nt][1] - mn0); sum0 += s[nt][1];
            s[nt][2] = ex2(s[nt][2] - mn1); sum1 += s[nt][2];
            s[nt][3] = ex2(s[nt][3] - mn1); sum1 += s[nt][3];
            o[nt][0] *= corr0; o[nt][1] *= corr0;
            o[nt][2] *= corr1; o[nt][3] *= corr1;
        }
        sum0 += __shfl_xor_sync(0xffffffffu, sum0, 1);
        sum0 += __shfl_xor_sync(0xffffffffu, sum0, 2);
        sum1 += __shfl_xor_sync(0xffffffffu, sum1, 1);
        sum1 += __shfl_xor_sync(0xffffffffu, sum1, 2);
        l_i[0] = l_i[0] * corr0 + sum0;
        l_i[1] = l_i[1] * corr1 + sum1;

        // ---- P -> A fragments (single fp16) ----
        uint32_t ph[4][4];
#pragma unroll
        for (int ks = 0; ks < 4; ks++) {
            ph[ks][0] = pack_h2(s[2 * ks][0],     s[2 * ks][1]);
            ph[ks][1] = pack_h2(s[2 * ks][2],     s[2 * ks][3]);
            ph[ks][2] = pack_h2(s[2 * ks + 1][0], s[2 * ks + 1][1]);
            ph[ks][3] = pack_h2(s[2 * ks + 1][2], s[2 * ks + 1][3]);
        }

        // ---- O += P V (1-term), V via ldmatrix.trans ----
#pragma unroll
        for (int ks = 0; ks < 4; ks++) {
#pragma unroll
            for (int dp = 0; dp < 4; dp++) {
                const uint32_t va = st + A_VH +
                    (uint32_t)(((ks * 16 + (t4 & 1) * 8 + r8) * A_LDH +
                                dp * 16 + (t4 >> 1) * 8) * 2);
                uint32_t vh[4];
                LDSM4T(vh[0], vh[1], vh[2], vh[3], va);
#pragma unroll
                for (int half = 0; half < 2; half++) {
                    const int nt = dp * 2 + half, hf = half * 2;
                    MMA16816(o[nt], ph[ks], vh[hf], vh[hf + 1]);
                }
            }
        }
    }

    // ---- normalize + write [B, NH, T, HS] ----
    const float inv0 = 1.0f / l_i[0];
    const float inv1 = 1.0f / l_i[1];
    const int r0 = qt * 64 + wid * 16 + g;
#pragma unroll
    for (int nt = 0; nt < 8; nt++) {
        const int col = nt * 8 + 2 * t;
        *reinterpret_cast<float2*>(out + base + (size_t)r0 * HS_ + col) =
            make_float2(o[nt][0] * inv0, o[nt][1] * inv0);
        *reinterpret_cast<float2*>(out + base + (size_t)(r0 + 8) * HS_ + col) =
            make_float2(o[nt][2] * inv1, o[nt][3] * inv1);
    }
}

// ---------------------------------------------------------------------------
extern "C" void kernel_launch(void* const* d_in, const int* in_sizes, int n_in,
                              void* d_out, int out_size)
{
    (void)in_sizes; (void)n_in; (void)out_size;
    const float* x    = (const float*)d_in[0];
    const float* w    = (const float*)d_in[1];
    const float* bias = (const float*)d_in[2];
    float* out = (float*)d_out;

    conv_x_kernel<<<(M_ * K_ / 4 + 255) / 256, 256>>>(x);
    conv_w_kernel<<<((K_ / 4) * N3_ + 255) / 256, 256>>>(w);

    cudaFuncSetAttribute(qkv_gemm_tc,
                         cudaFuncAttributeMaxDynamicSharedMemorySize, GEMM_SMEM);
    dim3 g1(N3_ / 128, M_ / 128);    // (18, 32)
    qkv_gemm_tc<<<g1, 256, GEMM_SMEM>>>(bias);

    cudaFuncSetAttribute(attn_tc,
                         cudaFuncAttributeMaxDynamicSharedMemorySize, ATTN_SMEM);
    dim3 g2(T_ / 64, NH_, B_);       // (32, 12, 2)
    attn_tc<<<g2, 128, ATTN_SMEM>>>(out);
}